// round 7
// baseline (speedup 1.0000x reference)
#include <cuda_runtime.h>
#include <cuda_fp16.h>
#include <stdint.h>
#include <math.h>

#define NTOK   (16 * 4096)   // 65536 tokens
#define D_IN   512
#define D_K    256
#define MSLOTS 64

// ---------------------------------------------------------------------------
// Scratch
// ---------------------------------------------------------------------------
__device__ __align__(256) __half g_E[(size_t)NTOK * D_K];     // encoded fp16
__device__ __align__(256) __half g_M[(size_t)NTOK * D_K];     // memory-read fp16
__device__ __align__(256) __half g_EW[D_K * D_IN];            // enc_w fp16
__device__ __align__(256) __half g_MEM[MSLOTS * D_K];         // mem fp16
__device__ __align__(256) __half g_MT[D_K * MSLOTS];          // mem^T fp16
__device__ __align__(256) __half g_DW[D_IN * D_K];            // dec_w fp16

// ---------------------------------------------------------------------------
// PTX helpers
// ---------------------------------------------------------------------------
__device__ __forceinline__ uint32_t smem_u32(const void* p) {
    uint32_t a;
    asm("{ .reg .u64 t; cvta.to.shared.u64 t, %1; cvt.u32.u64 %0, t; }"
        : "=r"(a) : "l"(p));
    return a;
}
__device__ __forceinline__ void cp16(uint32_t dst, const void* src) {
    asm volatile("cp.async.cg.shared.global [%0], [%1], 16;"
                 :: "r"(dst), "l"(src));
}
__device__ __forceinline__ void cp_commit() {
    asm volatile("cp.async.commit_group;");
}
__device__ __forceinline__ void cp_wait0() {
    asm volatile("cp.async.wait_group 0;" ::: "memory");
}

#define LDSM4(r0, r1, r2, r3, addr)                                            \
    asm volatile("ldmatrix.sync.aligned.m8n8.x4.shared.b16 {%0,%1,%2,%3}, [%4];" \
                 : "=r"(r0), "=r"(r1), "=r"(r2), "=r"(r3) : "r"(addr))
#define LDSM2(r0, r1, addr)                                                    \
    asm volatile("ldmatrix.sync.aligned.m8n8.x2.shared.b16 {%0,%1}, [%2];"     \
                 : "=r"(r0), "=r"(r1) : "r"(addr))
#define MMA16816(c, a, b)                                                      \
    asm volatile(                                                              \
        "mma.sync.aligned.m16n8k16.row.col.f32.f16.f16.f32 "                   \
        "{%0,%1,%2,%3},{%4,%5,%6,%7},{%8,%9},{%0,%1,%2,%3};"                   \
        : "+f"((c)[0]), "+f"((c)[1]), "+f"((c)[2]), "+f"((c)[3])               \
        : "r"((a)[0]), "r"((a)[1]), "r"((a)[2]), "r"((a)[3]),                  \
          "r"((b)[0]), "r"((b)[1]))

// ---------------------------------------------------------------------------
// K1: encoded = tanh(seq @ enc_w^T + enc_b), seq fp32 converted inline.
// CTA: 128 tokens x all 256 outputs. 256 threads, warps 2(m) x 4(n), NW=8.
// A: single fp16 buffer (LDG fp32 -> cvt -> STS). B: double-buffered cp.async.
// ---------------------------------------------------------------------------
__global__ __launch_bounds__(256)
void gemm1_enc(const float* __restrict__ seq,
               const __half* __restrict__ EW,
               const float* __restrict__ bias,
               __half* __restrict__ E)
{
    constexpr int OFF_A = 0;                 // 10240
    constexpr int OFF_B = 10240;             // 2 x 20480
    extern __shared__ char smem[];
    const uint32_t sb = smem_u32(smem);
    const int tid = threadIdx.x, lane = tid & 31, wid = tid >> 5;
    const int wm = wid & 1, wn = wid >> 1;
    const int m0 = blockIdx.x * 128;

    float c[4][8][4];
#pragma unroll
    for (int mi = 0; mi < 4; mi++)
#pragma unroll
        for (int ni = 0; ni < 8; ni++)
#pragma unroll
            for (int j = 0; j < 4; j++) c[mi][ni][j] = 0.f;

    // preload B chunk 0 (enc_w rows 0..255, k-cols 0..31)
    {
#pragma unroll
        for (int i = 0; i < 4; i++) {
            int e = tid + i * 256;
            int r = e >> 2, g = e & 3;
            cp16(sb + OFF_B + r * 80 + g * 16, EW + (size_t)r * 512 + g * 8);
        }
        cp_commit();
    }

    const uint32_t aRow = (uint32_t)((wm * 64 + (lane & 15)) * 80 + (lane >> 4) * 16);
    const uint32_t bRow = (uint32_t)((wn * 64 + (lane & 7)) * 80 + ((lane >> 3) & 1) * 16);

    for (int ch = 0; ch < 16; ch++) {
        // prefetch A chunk (fp32) into regs
        float4 av[4];
        int rr[4], gg[4];
#pragma unroll
        for (int i = 0; i < 4; i++) {
            int e = tid + i * 256;
            rr[i] = e >> 3; gg[i] = e & 7;
            av[i] = *(const float4*)(seq + (size_t)(m0 + rr[i]) * 512 + ch * 32 + gg[i] * 4);
        }
        cp_wait0();                  // B ch arrived
        __syncthreads();             // prev compute done -> A/B buffers free
        // store converted A
#pragma unroll
        for (int i = 0; i < 4; i++) {
            __half2 h01 = __floats2half2_rn(av[i].x, av[i].y);
            __half2 h23 = __floats2half2_rn(av[i].z, av[i].w);
            uint2 u;
            u.x = *(uint32_t*)&h01; u.y = *(uint32_t*)&h23;
            *(uint2*)(smem + OFF_A + rr[i] * 80 + gg[i] * 8) = u;
        }
        // issue B ch+1
        if (ch + 1 < 16) {
            const uint32_t st = sb + OFF_B + ((ch + 1) & 1) * 20480;
            const int kc = (ch + 1) * 32;
#pragma unroll
            for (int i = 0; i < 4; i++) {
                int e = tid + i * 256;
                int r = e >> 2, g = e & 3;
                cp16(st + r * 80 + g * 16, EW + (size_t)r * 512 + kc + g * 8);
            }
            cp_commit();
        }
        __syncthreads();             // A visible
        const uint32_t stB = sb + OFF_B + (ch & 1) * 20480;
#pragma unroll
        for (int kk = 0; kk < 2; kk++) {
            uint32_t a[4][4], b[8][2];
#pragma unroll
            for (int mi = 0; mi < 4; mi++) {
                uint32_t ad = sb + OFF_A + aRow + (uint32_t)(mi * 1280 + kk * 32);
                LDSM4(a[mi][0], a[mi][1], a[mi][2], a[mi][3], ad);
            }
#pragma unroll
            for (int ni = 0; ni < 8; ni++) {
                uint32_t bd = stB + bRow + (uint32_t)(ni * 640 + kk * 32);
                LDSM2(b[ni][0], b[ni][1], bd);
            }
#pragma unroll
            for (int mi = 0; mi < 4; mi++)
#pragma unroll
                for (int ni = 0; ni < 8; ni++)
                    MMA16816(c[mi][ni], a[mi], b[ni]);
        }
    }
    __syncthreads();

    const int r_in = lane >> 2, cpair = (lane & 3) * 2;
#pragma unroll
    for (int mi = 0; mi < 4; mi++) {
        const int rg = m0 + wm * 64 + mi * 16 + r_in;
#pragma unroll
        for (int ni = 0; ni < 8; ni++) {
            const int cg = wn * 64 + ni * 8 + cpair;
            float b0 = bias[cg], b1 = bias[cg + 1];
            float v0 = tanhf(c[mi][ni][0] + b0);
            float v1 = tanhf(c[mi][ni][1] + b1);
            float v2 = tanhf(c[mi][ni][2] + b0);
            float v3 = tanhf(c[mi][ni][3] + b1);
            *(__half2*)(E + (size_t)rg * 256 + cg)       = __floats2half2_rn(v0, v1);
            *(__half2*)(E + (size_t)(rg + 8) * 256 + cg) = __floats2half2_rn(v2, v3);
        }
    }
}

// ---------------------------------------------------------------------------
// K2: fused attention. Per CTA (128 tokens):
//   logits = E @ MEM^T (K=256); softmax; att -> d_out fp32;
//   memory = att @ MT (K=64) -> memo fp32 + M fp16.
// ---------------------------------------------------------------------------
__global__ __launch_bounds__(256)
void fused_attn(const __half* __restrict__ E,
                const __half* __restrict__ MEMp,
                const __half* __restrict__ MTp,
                float* __restrict__ att,
                float* __restrict__ memo,
                __half* __restrict__ M)
{
    constexpr int OFF_EA = 0;        // 2 x 10240
    constexpr int OFF_MB = 20480;    // 8 x 5120
    constexpr int OFF_MT = 61440;    // 2 x 20480
    constexpr int OFF_LG = 102400;   // 128 x 68 fp32 = 34816
    constexpr int OFF_AT = 137216;   // 2 x 10240
    extern __shared__ char smem[];
    const uint32_t sb = smem_u32(smem);
    const int tid = threadIdx.x, lane = tid & 31, wid = tid >> 5;
    const int wm = wid & 1, wn = wid >> 1;
    const int m0 = blockIdx.x * 128;
    const int r_in = lane >> 2, cpair = (lane & 3) * 2;

    // ---- preload: MEM (8 chunks), MT (2 chunks), E chunk 0
    {
        int r = tid >> 2, g = tid & 3;
#pragma unroll
        for (int ch = 0; ch < 8; ch++)
            cp16(sb + OFF_MB + ch * 5120 + r * 80 + g * 16,
                 MEMp + (size_t)r * 256 + ch * 32 + g * 8);
#pragma unroll
        for (int k = 0; k < 2; k++)
#pragma unroll
            for (int i = 0; i < 4; i++) {
                int e = tid + i * 256;
                int rr = e >> 2, gg = e & 3;
                cp16(sb + OFF_MT + k * 20480 + rr * 80 + gg * 16,
                     MTp + (size_t)rr * 64 + k * 32 + gg * 8);
            }
#pragma unroll
        for (int i = 0; i < 2; i++) {
            int e = tid + i * 256;
            int rr = e >> 2, gg = e & 3;
            cp16(sb + OFF_EA + rr * 80 + gg * 16,
                 E + (size_t)(m0 + rr) * 256 + gg * 8);
        }
        cp_commit();
    }

    // ---- stage 1: logits (NT=64: NW=2, NWC=16)
    float c1[4][2][4];
#pragma unroll
    for (int mi = 0; mi < 4; mi++)
#pragma unroll
        for (int ni = 0; ni < 2; ni++)
#pragma unroll
            for (int j = 0; j < 4; j++) c1[mi][ni][j] = 0.f;

    const uint32_t aRow  = (uint32_t)((wm * 64 + (lane & 15)) * 80 + (lane >> 4) * 16);
    const uint32_t bRow1 = (uint32_t)((wn * 16 + (lane & 7)) * 80 + ((lane >> 3) & 1) * 16);
    const uint32_t bRow2 = (uint32_t)((wn * 64 + (lane & 7)) * 80 + ((lane >> 3) & 1) * 16);

    for (int ch = 0; ch < 8; ch++) {
        cp_wait0();
        __syncthreads();
        if (ch + 1 < 8) {
            const uint32_t st = sb + OFF_EA + ((ch + 1) & 1) * 10240;
            const int kc = (ch + 1) * 32;
#pragma unroll
            for (int i = 0; i < 2; i++) {
                int e = tid + i * 256;
                int rr = e >> 2, gg = e & 3;
                cp16(st + rr * 80 + gg * 16,
                     E + (size_t)(m0 + rr) * 256 + kc + gg * 8);
            }
            cp_commit();
        }
        const uint32_t stA = sb + OFF_EA + (ch & 1) * 10240;
        const uint32_t stB = sb + OFF_MB + ch * 5120;
#pragma unroll
        for (int kk = 0; kk < 2; kk++) {
            uint32_t a[4][4], b[2][2];
#pragma unroll
            for (int mi = 0; mi < 4; mi++) {
                uint32_t ad = stA + aRow + (uint32_t)(mi * 1280 + kk * 32);
                LDSM4(a[mi][0], a[mi][1], a[mi][2], a[mi][3], ad);
            }
#pragma unroll
            for (int ni = 0; ni < 2; ni++) {
                uint32_t bd = stB + bRow1 + (uint32_t)(ni * 640 + kk * 32);
                LDSM2(b[ni][0], b[ni][1], bd);
            }
#pragma unroll
            for (int mi = 0; mi < 4; mi++)
#pragma unroll
                for (int ni = 0; ni < 2; ni++)
                    MMA16816(c1[mi][ni], a[mi], b[ni]);
        }
        __syncthreads();
    }

    // ---- epilogue 1: scaled logits -> smem
    float* LGf = (float*)(smem + OFF_LG);
#pragma unroll
    for (int mi = 0; mi < 4; mi++) {
        const int rl = wm * 64 + mi * 16 + r_in;
#pragma unroll
        for (int ni = 0; ni < 2; ni++) {
            const int cl = wn * 16 + ni * 8 + cpair;
            LGf[rl * 68 + cl]           = c1[mi][ni][0] * 0.0625f;
            LGf[rl * 68 + cl + 1]       = c1[mi][ni][1] * 0.0625f;
            LGf[(rl + 8) * 68 + cl]     = c1[mi][ni][2] * 0.0625f;
            LGf[(rl + 8) * 68 + cl + 1] = c1[mi][ni][3] * 0.0625f;
        }
    }
    __syncthreads();

    // ---- softmax: one thread per token row
    if (tid < 128) {
        float* lr = LGf + tid * 68;
        float mx = lr[0];
#pragma unroll 8
        for (int j = 1; j < 64; j++) mx = fmaxf(mx, lr[j]);
        float p[64], sum = 0.f;
#pragma unroll 8
        for (int j = 0; j < 64; j++) { p[j] = expf(lr[j] - mx); sum += p[j]; }
        float inv = 1.f / sum;
        __half* at0 = (__half*)(smem + OFF_AT);
#pragma unroll 8
        for (int j = 0; j < 64; j++) {
            float a = p[j] * inv;
            lr[j] = a;
            at0[((j >> 5) * 10240 + tid * 80 + (j & 31) * 2) >> 1] = __float2half_rn(a);
        }
    }
    __syncthreads();

    // ---- coalesced att fp32 write
#pragma unroll
    for (int i = 0; i < 32; i++) {
        int idx = tid + i * 256;
        int r = idx >> 6, cc = idx & 63;
        att[(size_t)(m0 + r) * 64 + cc] = LGf[r * 68 + cc];
    }

    // ---- stage 2: memory = att @ MT (NT=256: NW=8, K=64)
    float c2[4][8][4];
#pragma unroll
    for (int mi = 0; mi < 4; mi++)
#pragma unroll
        for (int ni = 0; ni < 8; ni++)
#pragma unroll
            for (int j = 0; j < 4; j++) c2[mi][ni][j] = 0.f;

#pragma unroll
    for (int ch = 0; ch < 2; ch++) {
        const uint32_t stA = sb + OFF_AT + ch * 10240;
        const uint32_t stB = sb + OFF_MT + ch * 20480;
#pragma unroll
        for (int kk = 0; kk < 2; kk++) {
            uint32_t a[4][4], b[8][2];
#pragma unroll
            for (int mi = 0; mi < 4; mi++) {
                uint32_t ad = stA + aRow + (uint32_t)(mi * 1280 + kk * 32);
                LDSM4(a[mi][0], a[mi][1], a[mi][2], a[mi][3], ad);
            }
#pragma unroll
            for (int ni = 0; ni < 8; ni++) {
                uint32_t bd = stB + bRow2 + (uint32_t)(ni * 640 + kk * 32);
                LDSM2(b[ni][0], b[ni][1], bd);
            }
#pragma unroll
            for (int mi = 0; mi < 4; mi++)
#pragma unroll
                for (int ni = 0; ni < 8; ni++)
                    MMA16816(c2[mi][ni], a[mi], b[ni]);
        }
    }

    // ---- epilogue 2: memo fp32 + M fp16
#pragma unroll
    for (int mi = 0; mi < 4; mi++) {
        const int rg = m0 + wm * 64 + mi * 16 + r_in;
#pragma unroll
        for (int ni = 0; ni < 8; ni++) {
            const int cg = wn * 64 + ni * 8 + cpair;
            float v0 = c2[mi][ni][0], v1 = c2[mi][ni][1];
            float v2 = c2[mi][ni][2], v3 = c2[mi][ni][3];
            *(float2*)(memo + (size_t)rg * 256 + cg)       = make_float2(v0, v1);
            *(float2*)(memo + (size_t)(rg + 8) * 256 + cg) = make_float2(v2, v3);
            *(__half2*)(M + (size_t)rg * 256 + cg)         = __floats2half2_rn(v0, v1);
            *(__half2*)(M + (size_t)(rg + 8) * 256 + cg)   = __floats2half2_rn(v2, v3);
        }
    }
}

// ---------------------------------------------------------------------------
// K3: recon = M @ dec_w^T + dec_b. Generic fp16 GEMM, NT=256, grid (2, 512).
// ---------------------------------------------------------------------------
__global__ __launch_bounds__(256)
void gemm_dec(const __half* __restrict__ A,
              const __half* __restrict__ B,
              const float* __restrict__ bias,
              float* __restrict__ Cf,
              int Ntotal, int K)
{
    constexpr int NT = 256, NW = 8;
    constexpr int A_BYTES = 10240, B_BYTES = NT * 80;
    constexpr int OFF_A = 0, OFF_B = A_BYTES;
    constexpr int STAGE = A_BYTES + B_BYTES;
    extern __shared__ char smem[];
    const uint32_t sb = smem_u32(smem);
    const int tid = threadIdx.x, lane = tid & 31, wid = tid >> 5;
    const int wm = wid & 1, wn = wid >> 1;
    const int m0 = blockIdx.y * 128;
    const int n0 = blockIdx.x * NT;

    float c[4][NW][4];
#pragma unroll
    for (int mi = 0; mi < 4; mi++)
#pragma unroll
        for (int ni = 0; ni < NW; ni++)
#pragma unroll
            for (int j = 0; j < 4; j++) c[mi][ni][j] = 0.f;

    const int nch = K >> 5;
    auto load_chunk = [&](int ch) {
        const uint32_t st = sb + (uint32_t)((ch & 1) * STAGE);
        const int kc = ch * 32;
#pragma unroll
        for (int i = 0; i < 2; i++) {
            int e = tid + i * 256;
            int r = e >> 2, g = e & 3;
            cp16(st + OFF_A + (uint32_t)(r * 80 + g * 16),
                 A + (size_t)(m0 + r) * K + kc + g * 8);
        }
#pragma unroll
        for (int i = 0; i < 4; i++) {
            int e = tid + i * 256;
            int r = e >> 2, g = e & 3;
            cp16(st + OFF_B + (uint32_t)(r * 80 + g * 16),
                 B + (size_t)(n0 + r) * K + kc + g * 8);
        }
        cp_commit();
    };

    load_chunk(0);
    const uint32_t aRow = (uint32_t)((wm * 64 + (lane & 15)) * 80 + (lane >> 4) * 16);
    const uint32_t bRow = (uint32_t)((wn * 64 + (lane & 7)) * 80 + ((lane >> 3) & 1) * 16);

    for (int ch = 0; ch < nch; ch++) {
        cp_wait0();
        __syncthreads();
        if (ch + 1 < nch) load_chunk(ch + 1);
        const uint32_t st = sb + (uint32_t)((ch & 1) * STAGE);
#pragma unroll
        for (int kk = 0; kk < 2; kk++) {
            uint32_t a[4][4], b[NW][2];
#pragma unroll
            for (int mi = 0; mi < 4; mi++) {
                uint32_t ad = st + OFF_A + aRow + (uint32_t)(mi * 1280 + kk * 32);
                LDSM4(a[mi][0], a[mi][1], a[mi][2], a[mi][3], ad);
            }
#pragma unroll
            for (int ni = 0; ni < NW; ni++) {
                uint32_t bd = st + OFF_B + bRow + (uint32_t)(ni * 640 + kk * 32);
                LDSM2(b[ni][0], b[ni][1], bd);
            }
#pragma unroll
            for (int mi = 0; mi < 4; mi++)
#pragma unroll
                for (int ni = 0; ni < NW; ni++)
                    MMA16816(c[mi][ni], a[mi], b[ni]);
        }
        __syncthreads();
    }

    const int r_in = lane >> 2, cpair = (lane & 3) * 2;
#pragma unroll
    for (int mi = 0; mi < 4; mi++) {
        const int rg = m0 + wm * 64 + mi * 16 + r_in;
#pragma unroll
        for (int ni = 0; ni < NW; ni++) {
            const int cg = n0 + wn * 64 + ni * 8 + cpair;
            float b0 = bias[cg], b1 = bias[cg + 1];
            float v0 = c[mi][ni][0] + b0, v1 = c[mi][ni][1] + b1;
            float v2 = c[mi][ni][2] + b0, v3 = c[mi][ni][3] + b1;
            *(float2*)(Cf + (size_t)rg * Ntotal + cg)       = make_float2(v0, v1);
            *(float2*)(Cf + (size_t)(rg + 8) * Ntotal + cg) = make_float2(v2, v3);
        }
    }
}

// ---------------------------------------------------------------------------
// weight conversions (tiny)
// ---------------------------------------------------------------------------
__global__ void cvt_half4(const float4* __restrict__ x, __half2* __restrict__ h, int n4)
{
    int i = blockIdx.x * blockDim.x + threadIdx.x;
    if (i >= n4) return;
    float4 v = x[i];
    h[2*i]   = __floats2half2_rn(v.x, v.y);
    h[2*i+1] = __floats2half2_rn(v.z, v.w);
}
__global__ void cvt_halfT(const float* __restrict__ x, __half* __restrict__ h,
                          int rows, int cols)
{
    int i = blockIdx.x * blockDim.x + threadIdx.x;
    if (i >= rows * cols) return;
    int r = i / cols, cidx = i % cols;
    h[(size_t)cidx * rows + r] = __float2half_rn(x[i]);
}

// ---------------------------------------------------------------------------
// launch
// ---------------------------------------------------------------------------
extern "C" void kernel_launch(void* const* d_in, const int* in_sizes, int n_in,
                              void* d_out, int out_size)
{
    const float* seq   = (const float*)d_in[0];
    const float* enc_w = (const float*)d_in[1];
    const float* enc_b = (const float*)d_in[2];
    const float* mem   = (const float*)d_in[3];
    const float* dec_w = (const float*)d_in[4];
    const float* dec_b = (const float*)d_in[5];

    float* out   = (float*)d_out;
    float* recon = out;
    float* att   = out + (size_t)NTOK * D_IN;
    float* memo  = att + (size_t)NTOK * MSLOTS;

    __half *E, *M, *EW, *MEM, *MT, *DW;
    cudaGetSymbolAddress((void**)&E, g_E);
    cudaGetSymbolAddress((void**)&M, g_M);
    cudaGetSymbolAddress((void**)&EW, g_EW);
    cudaGetSymbolAddress((void**)&MEM, g_MEM);
    cudaGetSymbolAddress((void**)&MT, g_MT);
    cudaGetSymbolAddress((void**)&DW, g_DW);

    const int SM_G1 = 10240 + 2 * 20480;               // 51200
    const int SM_AT = 137216 + 2 * 10240;              // 157696
    const int SM_G3 = 2 * (10240 + 256 * 80);          // 61440
    cudaFuncSetAttribute(gemm1_enc,  cudaFuncAttributeMaxDynamicSharedMemorySize, SM_G1);
    cudaFuncSetAttribute(fused_attn, cudaFuncAttributeMaxDynamicSharedMemorySize, SM_AT);
    cudaFuncSetAttribute(gemm_dec,   cudaFuncAttributeMaxDynamicSharedMemorySize, SM_G3);

    // weight conversions
    {
        int n4 = D_K * D_IN / 4;
        cvt_half4<<<(n4 + 255) / 256, 256>>>((const float4*)enc_w, (__half2*)EW, n4);
        n4 = MSLOTS * D_K / 4;
        cvt_half4<<<(n4 + 255) / 256, 256>>>((const float4*)mem, (__half2*)MEM, n4);
        cvt_halfT<<<(MSLOTS * D_K + 255) / 256, 256>>>(mem, MT, MSLOTS, D_K);
        n4 = D_IN * D_K / 4;
        cvt_half4<<<(n4 + 255) / 256, 256>>>((const float4*)dec_w, (__half2*)DW, n4);
    }

    // 1) encode (fused fp32->fp16 conversion of seq)
    gemm1_enc<<<NTOK / 128, 256, SM_G1>>>(seq, EW, enc_b, E);

    // 2) fused attention: logits + softmax + memory read
    fused_attn<<<NTOK / 128, 256, SM_AT>>>(E, MEM, MT, att, memo, M);

    // 3) decode
    {
        dim3 grid(D_IN / 256, NTOK / 128);
        gemm_dec<<<grid, 256, SM_G3>>>(M, DW, dec_b, recon, D_IN, D_K);
    }
}

// round 9
// speedup vs baseline: 1.0886x; 1.0886x over previous
#include <cuda_runtime.h>
#include <cuda_fp16.h>
#include <stdint.h>
#include <math.h>

#define NTOK   (16 * 4096)   // 65536 tokens
#define D_IN   512
#define D_K    256
#define MSLOTS 64

// ---------------------------------------------------------------------------
// Scratch (fp16 representations)
// ---------------------------------------------------------------------------
__device__ __align__(256) __half g_S[(size_t)NTOK * D_IN];    // seq fp16
__device__ __align__(256) __half g_E[(size_t)NTOK * D_K];     // encoded fp16
__device__ __align__(256) __half g_AT[(size_t)NTOK * MSLOTS]; // attention fp16
__device__ __align__(256) __half g_M[(size_t)NTOK * D_K];     // memory-read fp16
__device__ __align__(256) __half g_EW[D_K * D_IN];            // enc_w fp16
__device__ __align__(256) __half g_MEM[MSLOTS * D_K];         // mem fp16
__device__ __align__(256) __half g_MT[D_K * MSLOTS];          // mem^T fp16
__device__ __align__(256) __half g_DW[D_IN * D_K];            // dec_w fp16

// ---------------------------------------------------------------------------
// PTX helpers
// ---------------------------------------------------------------------------
__device__ __forceinline__ uint32_t smem_u32(const void* p) {
    uint32_t a;
    asm("{ .reg .u64 t; cvta.to.shared.u64 t, %1; cvt.u32.u64 %0, t; }"
        : "=r"(a) : "l"(p));
    return a;
}
__device__ __forceinline__ void cp16(uint32_t dst, const void* src) {
    asm volatile("cp.async.cg.shared.global [%0], [%1], 16;"
                 :: "r"(dst), "l"(src));
}
__device__ __forceinline__ void cp_commit() {
    asm volatile("cp.async.commit_group;");
}
__device__ __forceinline__ void cp_wait0() {
    asm volatile("cp.async.wait_group 0;" ::: "memory");
}

#define LDSM4(r0, r1, r2, r3, addr)                                            \
    asm volatile("ldmatrix.sync.aligned.m8n8.x4.shared.b16 {%0,%1,%2,%3}, [%4];" \
                 : "=r"(r0), "=r"(r1), "=r"(r2), "=r"(r3) : "r"(addr))
#define LDSM2(r0, r1, addr)                                                    \
    asm volatile("ldmatrix.sync.aligned.m8n8.x2.shared.b16 {%0,%1}, [%2];"     \
                 : "=r"(r0), "=r"(r1) : "r"(addr))
#define MMA16816(c, a, b)                                                      \
    asm volatile(                                                              \
        "mma.sync.aligned.m16n8k16.row.col.f32.f16.f16.f32 "                   \
        "{%0,%1,%2,%3},{%4,%5,%6,%7},{%8,%9},{%0,%1,%2,%3};"                   \
        : "+f"((c)[0]), "+f"((c)[1]), "+f"((c)[2]), "+f"((c)[3])               \
        : "r"((a)[0]), "r"((a)[1]), "r"((a)[2]), "r"((a)[3]),                  \
          "r"((b)[0]), "r"((b)[1]))

// ---------------------------------------------------------------------------
// fp16 GEMM via mma.sync (round-6 proven template)
// C[M, Ntotal] = epi(A @ B^T + bias); CTA 128 x NT, BK=32, 256 thr, 2x4 warps.
// EPI: 0 = +bias, tanh, write fp16 (Ch)
//      2 = identity, write fp32 (Cf) AND fp16 (Ch)
//      3 = +bias, write fp32 (Cf)
// ---------------------------------------------------------------------------
template <int NT, int EPI>
__global__ __launch_bounds__(256)
void mma_gemm(const __half* __restrict__ A,
              const __half* __restrict__ B,
              const float* __restrict__ bias,
              float* __restrict__ Cf,
              __half* __restrict__ Ch,
              int Ntotal, int K)
{
    constexpr int NW  = NT / 32;
    constexpr int NWC = NT / 4;
    constexpr int A_BYTES = 128 * 40 * 2;  // 10240
    constexpr int B_BYTES = NT * 40 * 2;
    constexpr int OFF_A = 0, OFF_B = A_BYTES;
    constexpr int STAGE = A_BYTES + B_BYTES;

    extern __shared__ char smem[];
    const uint32_t sb = smem_u32(smem);

    const int tid  = threadIdx.x;
    const int lane = tid & 31;
    const int wid  = tid >> 5;
    const int wm   = wid & 1;
    const int wn   = wid >> 1;
    const int m0   = blockIdx.y * 128;
    const int n0   = blockIdx.x * NT;

    float c[4][NW][4];
#pragma unroll
    for (int mi = 0; mi < 4; mi++)
#pragma unroll
        for (int ni = 0; ni < NW; ni++)
#pragma unroll
            for (int j = 0; j < 4; j++) c[mi][ni][j] = 0.f;

    const int nch = K >> 5;

    auto load_chunk = [&](int ch) {
        const uint32_t st = sb + (uint32_t)((ch & 1) * STAGE);
        const int kc = ch * 32;
#pragma unroll
        for (int i = 0; i < 2; i++) {
            int e = tid + i * 256;
            int r = e >> 2, g = e & 3;
            uint32_t d = st + (uint32_t)(r * 80 + g * 16);
            size_t go = (size_t)(m0 + r) * K + kc + g * 8;
            cp16(d + OFF_A, A + go);
        }
#pragma unroll
        for (int i = 0; i < NT / 64; i++) {
            int e = tid + i * 256;
            int r = e >> 2, g = e & 3;
            uint32_t d = st + (uint32_t)(r * 80 + g * 16);
            size_t go = (size_t)(n0 + r) * K + kc + g * 8;
            cp16(d + OFF_B, B + go);
        }
        cp_commit();
    };

    load_chunk(0);

    const uint32_t aRow = (uint32_t)((wm * 64 + (lane & 15)) * 80 + (lane >> 4) * 16);
    const uint32_t bRow = (uint32_t)((wn * NWC + (lane & 7)) * 80 + ((lane >> 3) & 1) * 16);

    for (int ch = 0; ch < nch; ch++) {
        cp_wait0();
        __syncthreads();
        if (ch + 1 < nch) load_chunk(ch + 1);

        const uint32_t st = sb + (uint32_t)((ch & 1) * STAGE);
#pragma unroll
        for (int kk = 0; kk < 2; kk++) {
            uint32_t a[4][4], b[NW][2];
#pragma unroll
            for (int mi = 0; mi < 4; mi++) {
                uint32_t ad = st + aRow + (uint32_t)(mi * 1280 + kk * 32);
                LDSM4(a[mi][0], a[mi][1], a[mi][2], a[mi][3], ad + OFF_A);
            }
#pragma unroll
            for (int ni = 0; ni < NW; ni++) {
                uint32_t bd = st + bRow + (uint32_t)(ni * 640 + kk * 32);
                LDSM2(b[ni][0], b[ni][1], bd + OFF_B);
            }
#pragma unroll
            for (int mi = 0; mi < 4; mi++)
#pragma unroll
                for (int ni = 0; ni < NW; ni++)
                    MMA16816(c[mi][ni], a[mi], b[ni]);
        }
        __syncthreads();
    }

    const int r_in  = lane >> 2;
    const int cpair = (lane & 3) * 2;
#pragma unroll
    for (int mi = 0; mi < 4; mi++) {
        const int rg = m0 + wm * 64 + mi * 16 + r_in;
#pragma unroll
        for (int ni = 0; ni < NW; ni++) {
            const int cg = n0 + wn * NWC + ni * 8 + cpair;
            float v0 = c[mi][ni][0], v1 = c[mi][ni][1];
            float v2 = c[mi][ni][2], v3 = c[mi][ni][3];
            if (EPI == 0 || EPI == 3) {
                float b0 = bias[cg], b1 = bias[cg + 1];
                v0 += b0; v1 += b1; v2 += b0; v3 += b1;
            }
            if (EPI == 0) {
                v0 = tanhf(v0); v1 = tanhf(v1); v2 = tanhf(v2); v3 = tanhf(v3);
            }
            if (EPI == 2 || EPI == 3) {
                float2* p0 = (float2*)(Cf + (size_t)rg * Ntotal + cg);
                float2* p1 = (float2*)(Cf + (size_t)(rg + 8) * Ntotal + cg);
                *p0 = make_float2(v0, v1);
                *p1 = make_float2(v2, v3);
            }
            if (EPI == 0 || EPI == 2) {
                __half2 h0 = __floats2half2_rn(v0, v1);
                __half2 h1 = __floats2half2_rn(v2, v3);
                *(__half2*)(Ch + (size_t)rg * Ntotal + cg)       = h0;
                *(__half2*)(Ch + (size_t)(rg + 8) * Ntotal + cg) = h1;
            }
        }
    }
}

// ---------------------------------------------------------------------------
// Fused logits + softmax: per CTA (128 tokens)
//   logits = E @ MEM^T / 16 -> smem; softmax; att fp32 (d_out) + AT fp16.
// Same GEMM mainloop as mma_gemm<64>, epilogue replaced. smem = 65.5 KB.
// ---------------------------------------------------------------------------
__global__ __launch_bounds__(256)
void logits_softmax(const __half* __restrict__ E,
                    const __half* __restrict__ MEMp,
                    float* __restrict__ att,
                    __half* __restrict__ AT)
{
    constexpr int A_BYTES = 10240, B_BYTES = 64 * 80;  // 5120
    constexpr int OFF_A = 0, OFF_B = A_BYTES;
    constexpr int STAGE = A_BYTES + B_BYTES;           // 15360
    constexpr int OFF_LG = 2 * STAGE;                  // 30720

    extern __shared__ char smem[];
    const uint32_t sb = smem_u32(smem);
    const int tid = threadIdx.x, lane = tid & 31, wid = tid >> 5;
    const int wm = wid & 1, wn = wid >> 1;
    const int m0 = blockIdx.x * 128;

    float c[4][2][4];
#pragma unroll
    for (int mi = 0; mi < 4; mi++)
#pragma unroll
        for (int ni = 0; ni < 2; ni++)
#pragma unroll
            for (int j = 0; j < 4; j++) c[mi][ni][j] = 0.f;

    auto load_chunk = [&](int ch) {
        const uint32_t st = sb + (uint32_t)((ch & 1) * STAGE);
        const int kc = ch * 32;
#pragma unroll
        for (int i = 0; i < 2; i++) {
            int e = tid + i * 256;
            int r = e >> 2, g = e & 3;
            cp16(st + OFF_A + (uint32_t)(r * 80 + g * 16),
                 E + (size_t)(m0 + r) * D_K + kc + g * 8);
        }
        {
            int r = tid >> 2, g = tid & 3;
            if (r < 64)
                cp16(st + OFF_B + (uint32_t)(r * 80 + g * 16),
                     MEMp + (size_t)r * D_K + kc + g * 8);
        }
        cp_commit();
    };

    load_chunk(0);

    const uint32_t aRow = (uint32_t)((wm * 64 + (lane & 15)) * 80 + (lane >> 4) * 16);
    const uint32_t bRow = (uint32_t)((wn * 16 + (lane & 7)) * 80 + ((lane >> 3) & 1) * 16);

    for (int ch = 0; ch < 8; ch++) {
        cp_wait0();
        __syncthreads();
        if (ch + 1 < 8) load_chunk(ch + 1);

        const uint32_t st = sb + (uint32_t)((ch & 1) * STAGE);
#pragma unroll
        for (int kk = 0; kk < 2; kk++) {
            uint32_t a[4][4], b[2][2];
#pragma unroll
            for (int mi = 0; mi < 4; mi++) {
                uint32_t ad = st + OFF_A + aRow + (uint32_t)(mi * 1280 + kk * 32);
                LDSM4(a[mi][0], a[mi][1], a[mi][2], a[mi][3], ad);
            }
#pragma unroll
            for (int ni = 0; ni < 2; ni++) {
                uint32_t bd = st + OFF_B + bRow + (uint32_t)(ni * 640 + kk * 32);
                LDSM2(b[ni][0], b[ni][1], bd);
            }
#pragma unroll
            for (int mi = 0; mi < 4; mi++)
#pragma unroll
                for (int ni = 0; ni < 2; ni++)
                    MMA16816(c[mi][ni], a[mi], b[ni]);
        }
        __syncthreads();
    }

    // ---- scaled logits -> smem (pitch 68 floats to avoid conflicts)
    float* LGf = (float*)(smem + OFF_LG);
    const int r_in = lane >> 2, cpair = (lane & 3) * 2;
#pragma unroll
    for (int mi = 0; mi < 4; mi++) {
        const int rl = wm * 64 + mi * 16 + r_in;
#pragma unroll
        for (int ni = 0; ni < 2; ni++) {
            const int cl = wn * 16 + ni * 8 + cpair;
            LGf[rl * 68 + cl]           = c[mi][ni][0] * 0.0625f;
            LGf[rl * 68 + cl + 1]       = c[mi][ni][1] * 0.0625f;
            LGf[(rl + 8) * 68 + cl]     = c[mi][ni][2] * 0.0625f;
            LGf[(rl + 8) * 68 + cl + 1] = c[mi][ni][3] * 0.0625f;
        }
    }
    __syncthreads();

    // ---- softmax: 2 threads per row (tid>>1 = row, tid&1 = half)
    {
        const int row = tid >> 1, half = tid & 1;
        float* lr = LGf + row * 68 + half * 32;
        float mx = lr[0];
#pragma unroll 8
        for (int j = 1; j < 32; j++) mx = fmaxf(mx, lr[j]);
        float omx = __shfl_xor_sync(0xffffffffu, mx, 1);
        mx = fmaxf(mx, omx);
        float sum = 0.f;
#pragma unroll 8
        for (int j = 0; j < 32; j++) {
            float p = expf(lr[j] - mx);
            lr[j] = p;
            sum += p;
        }
        sum += __shfl_xor_sync(0xffffffffu, sum, 1);
        float inv = 1.f / sum;
#pragma unroll 8
        for (int j = 0; j < 32; j++) lr[j] *= inv;
    }
    __syncthreads();

    // ---- coalesced writes: att fp32 (d_out) + AT fp16
#pragma unroll
    for (int i = 0; i < 32; i++) {
        int idx = tid + i * 256;
        int r = idx >> 6, cc = idx & 63;
        float v = LGf[r * 68 + cc];
        att[(size_t)(m0 + r) * 64 + cc] = v;
        AT[(size_t)(m0 + r) * 64 + cc]  = __float2half_rn(v);
    }
}

// ---------------------------------------------------------------------------
// fp32 -> fp16 conversions
// ---------------------------------------------------------------------------
__global__ void cvt_half4(const float4* __restrict__ x,
                          __half2* __restrict__ h, int n4)
{
    int i = blockIdx.x * blockDim.x + threadIdx.x;
    if (i >= n4) return;
    float4 v = x[i];
    h[2*i]   = __floats2half2_rn(v.x, v.y);
    h[2*i+1] = __floats2half2_rn(v.z, v.w);
}
__global__ void cvt_halfT(const float* __restrict__ x,
                          __half* __restrict__ h, int rows, int cols)
{
    int i = blockIdx.x * blockDim.x + threadIdx.x;
    if (i >= rows * cols) return;
    int r = i / cols, cidx = i % cols;
    h[(size_t)cidx * rows + r] = __float2half_rn(x[i]);
}

// ---------------------------------------------------------------------------
// launch
// ---------------------------------------------------------------------------
extern "C" void kernel_launch(void* const* d_in, const int* in_sizes, int n_in,
                              void* d_out, int out_size)
{
    const float* seq   = (const float*)d_in[0];
    const float* enc_w = (const float*)d_in[1];
    const float* enc_b = (const float*)d_in[2];
    const float* mem   = (const float*)d_in[3];
    const float* dec_w = (const float*)d_in[4];
    const float* dec_b = (const float*)d_in[5];

    float* out   = (float*)d_out;
    float* recon = out;
    float* att   = out + (size_t)NTOK * D_IN;
    float* memo  = att + (size_t)NTOK * MSLOTS;

    __half *S, *E, *AT, *M, *EW, *MEM, *MT, *DW;
    cudaGetSymbolAddress((void**)&S, g_S);
    cudaGetSymbolAddress((void**)&E, g_E);
    cudaGetSymbolAddress((void**)&AT, g_AT);
    cudaGetSymbolAddress((void**)&M, g_M);
    cudaGetSymbolAddress((void**)&EW, g_EW);
    cudaGetSymbolAddress((void**)&MEM, g_MEM);
    cudaGetSymbolAddress((void**)&MT, g_MT);
    cudaGetSymbolAddress((void**)&DW, g_DW);

    const int SM128 = 2 * (10240 + 128 * 80);          // 40960
    const int SM_LS = 2 * (10240 + 64 * 80) + 34816;   // 65536
    cudaFuncSetAttribute(mma_gemm<128, 0>, cudaFuncAttributeMaxDynamicSharedMemorySize, SM128);
    cudaFuncSetAttribute(logits_softmax,   cudaFuncAttributeMaxDynamicSharedMemorySize, SM_LS);
    cudaFuncSetAttribute(mma_gemm<128, 2>, cudaFuncAttributeMaxDynamicSharedMemorySize, SM128);
    cudaFuncSetAttribute(mma_gemm<128, 3>, cudaFuncAttributeMaxDynamicSharedMemorySize, SM128);

    // conversions
    {
        int n4 = NTOK * D_IN / 4;
        cvt_half4<<<(n4 + 255) / 256, 256>>>((const float4*)seq, (__half2*)S, n4);
        n4 = D_K * D_IN / 4;
        cvt_half4<<<(n4 + 255) / 256, 256>>>((const float4*)enc_w, (__half2*)EW, n4);
        n4 = MSLOTS * D_K / 4;
        cvt_half4<<<(n4 + 255) / 256, 256>>>((const float4*)mem, (__half2*)MEM, n4);
        cvt_halfT<<<(MSLOTS * D_K + 255) / 256, 256>>>(mem, MT, MSLOTS, D_K);
        n4 = D_IN * D_K / 4;
        cvt_half4<<<(n4 + 255) / 256, 256>>>((const float4*)dec_w, (__half2*)DW, n4);
    }

    // 1) encoded = tanh(seq @ enc_w^T + enc_b) -> fp16
    {
        dim3 grid(D_K / 128, NTOK / 128);
        mma_gemm<128, 0><<<grid, 256, SM128>>>(S, EW, enc_b, nullptr, E,
                                               D_K, D_IN);
    }
    // 2) fused logits + softmax -> att fp32 (d_out) + AT fp16
    logits_softmax<<<NTOK / 128, 256, SM_LS>>>(E, MEM, att, AT);

    // 3) memory = att @ mem -> memo fp32 (d_out) + M fp16
    {
        dim3 grid(D_K / 128, NTOK / 128);
        mma_gemm<128, 2><<<grid, 256, SM128>>>(AT, MT, nullptr, memo, M,
                                               D_K, MSLOTS);
    }
    // 4) recon = M @ dec_w^T + dec_b -> fp32 (d_out)
    {
        dim3 grid(D_IN / 128, NTOK / 128);
        mma_gemm<128, 3><<<grid, 256, SM128>>>(M, DW, dec_b, recon, nullptr,
                                               D_IN, D_K);
    }
}

// round 10
// speedup vs baseline: 1.1506x; 1.0570x over previous
#include <cuda_runtime.h>
#include <cuda_fp16.h>
#include <stdint.h>
#include <math.h>

#define NTOK   (16 * 4096)   // 65536 tokens
#define D_IN   512
#define D_K    256
#define MSLOTS 64

// ---------------------------------------------------------------------------
// Scratch (fp16 representations)
// ---------------------------------------------------------------------------
__device__ __align__(256) __half g_S[(size_t)NTOK * D_IN];    // seq fp16
__device__ __align__(256) __half g_E[(size_t)NTOK * D_K];     // encoded fp16
__device__ __align__(256) __half g_AT[(size_t)NTOK * MSLOTS]; // attention fp16
__device__ __align__(256) __half g_M[(size_t)NTOK * D_K];     // memory-read fp16
__device__ __align__(256) __half g_EW[D_K * D_IN];            // enc_w fp16
__device__ __align__(256) __half g_MEM[MSLOTS * D_K];         // mem fp16
__device__ __align__(256) __half g_MT[D_K * MSLOTS];          // mem^T fp16
__device__ __align__(256) __half g_DW[D_IN * D_K];            // dec_w fp16

// ---------------------------------------------------------------------------
// PTX helpers
// ---------------------------------------------------------------------------
__device__ __forceinline__ uint32_t smem_u32(const void* p) {
    uint32_t a;
    asm("{ .reg .u64 t; cvta.to.shared.u64 t, %1; cvt.u32.u64 %0, t; }"
        : "=r"(a) : "l"(p));
    return a;
}
__device__ __forceinline__ void cp16(uint32_t dst, const void* src) {
    asm volatile("cp.async.cg.shared.global [%0], [%1], 16;"
                 :: "r"(dst), "l"(src));
}
__device__ __forceinline__ void cp_commit() {
    asm volatile("cp.async.commit_group;");
}
__device__ __forceinline__ void cp_wait0() {
    asm volatile("cp.async.wait_group 0;" ::: "memory");
}
__device__ __forceinline__ void cp_wait1() {
    asm volatile("cp.async.wait_group 1;" ::: "memory");
}

#define LDSM4(r0, r1, r2, r3, addr)                                            \
    asm volatile("ldmatrix.sync.aligned.m8n8.x4.shared.b16 {%0,%1,%2,%3}, [%4];" \
                 : "=r"(r0), "=r"(r1), "=r"(r2), "=r"(r3) : "r"(addr))
#define LDSM2(r0, r1, addr)                                                    \
    asm volatile("ldmatrix.sync.aligned.m8n8.x2.shared.b16 {%0,%1}, [%2];"     \
                 : "=r"(r0), "=r"(r1) : "r"(addr))
#define MMA16816(c, a, b)                                                      \
    asm volatile(                                                              \
        "mma.sync.aligned.m16n8k16.row.col.f32.f16.f16.f32 "                   \
        "{%0,%1,%2,%3},{%4,%5,%6,%7},{%8,%9},{%0,%1,%2,%3};"                   \
        : "+f"((c)[0]), "+f"((c)[1]), "+f"((c)[2]), "+f"((c)[3])               \
        : "r"((a)[0]), "r"((a)[1]), "r"((a)[2]), "r"((a)[3]),                  \
          "r"((b)[0]), "r"((b)[1]))

// ---------------------------------------------------------------------------
// fp16 GEMM, 3-stage cp.async pipeline (wait_group 1, in-order completion).
// C[M, Ntotal] = epi(A @ B^T + bias); CTA 128 x NT, BK=32, 256 thr, 2x4 warps.
// EPI: 0 = +bias, tanh, write fp16 (Ch)
//      2 = identity, write fp32 (Cf) AND fp16 (Ch)
//      3 = +bias, write fp32 (Cf)
// ---------------------------------------------------------------------------
template <int NT, int EPI>
__global__ __launch_bounds__(256, 2)
void mma_gemm(const __half* __restrict__ A,
              const __half* __restrict__ B,
              const float* __restrict__ bias,
              float* __restrict__ Cf,
              __half* __restrict__ Ch,
              int Ntotal, int K)
{
    constexpr int NW  = NT / 32;
    constexpr int NWC = NT / 4;
    constexpr int A_BYTES = 128 * 40 * 2;  // 10240
    constexpr int B_BYTES = NT * 40 * 2;
    constexpr int OFF_A = 0, OFF_B = A_BYTES;
    constexpr int STAGE = A_BYTES + B_BYTES;

    extern __shared__ char smem[];
    const uint32_t sb = smem_u32(smem);

    const int tid  = threadIdx.x;
    const int lane = tid & 31;
    const int wid  = tid >> 5;
    const int wm   = wid & 1;
    const int wn   = wid >> 1;
    const int m0   = blockIdx.y * 128;
    const int n0   = blockIdx.x * NT;

    float c[4][NW][4];
#pragma unroll
    for (int mi = 0; mi < 4; mi++)
#pragma unroll
        for (int ni = 0; ni < NW; ni++)
#pragma unroll
            for (int j = 0; j < 4; j++) c[mi][ni][j] = 0.f;

    const int nch = K >> 5;

    // always commits (empty group beyond range) -> uniform wait_group count
    auto load_chunk = [&](int ch) {
        if (ch < nch) {
            const uint32_t st = sb + (uint32_t)((ch % 3) * STAGE);
            const int kc = ch * 32;
#pragma unroll
            for (int i = 0; i < 2; i++) {
                int e = tid + i * 256;
                int r = e >> 2, g = e & 3;
                cp16(st + OFF_A + (uint32_t)(r * 80 + g * 16),
                     A + (size_t)(m0 + r) * K + kc + g * 8);
            }
#pragma unroll
            for (int i = 0; i < NT / 64; i++) {
                int e = tid + i * 256;
                int r = e >> 2, g = e & 3;
                cp16(st + OFF_B + (uint32_t)(r * 80 + g * 16),
                     B + (size_t)(n0 + r) * K + kc + g * 8);
            }
        }
        cp_commit();
    };

    load_chunk(0);
    load_chunk(1);

    const uint32_t aRow = (uint32_t)((wm * 64 + (lane & 15)) * 80 + (lane >> 4) * 16);
    const uint32_t bRow = (uint32_t)((wn * NWC + (lane & 7)) * 80 + ((lane >> 3) & 1) * 16);

    for (int ch = 0; ch < nch; ch++) {
        cp_wait1();              // chunk ch ready (ch+1 may be in flight)
        __syncthreads();         // all warps done with stage (ch+3)%3 == ch%3... (prev compute)
        load_chunk(ch + 2);      // refill stage (ch+2)%3 (free since compute ch-1 done)

        const uint32_t st = sb + (uint32_t)((ch % 3) * STAGE);
#pragma unroll
        for (int kk = 0; kk < 2; kk++) {
            uint32_t a[4][4], b[NW][2];
#pragma unroll
            for (int mi = 0; mi < 4; mi++) {
                uint32_t ad = st + OFF_A + aRow + (uint32_t)(mi * 1280 + kk * 32);
                LDSM4(a[mi][0], a[mi][1], a[mi][2], a[mi][3], ad);
            }
#pragma unroll
            for (int ni = 0; ni < NW; ni++) {
                uint32_t bd = st + OFF_B + bRow + (uint32_t)(ni * 640 + kk * 32);
                LDSM2(b[ni][0], b[ni][1], bd);
            }
#pragma unroll
            for (int mi = 0; mi < 4; mi++)
#pragma unroll
                for (int ni = 0; ni < NW; ni++)
                    MMA16816(c[mi][ni], a[mi], b[ni]);
        }
    }

    const int r_in  = lane >> 2;
    const int cpair = (lane & 3) * 2;
#pragma unroll
    for (int mi = 0; mi < 4; mi++) {
        const int rg = m0 + wm * 64 + mi * 16 + r_in;
#pragma unroll
        for (int ni = 0; ni < NW; ni++) {
            const int cg = n0 + wn * NWC + ni * 8 + cpair;
            float v0 = c[mi][ni][0], v1 = c[mi][ni][1];
            float v2 = c[mi][ni][2], v3 = c[mi][ni][3];
            if (EPI == 0 || EPI == 3) {
                float b0 = bias[cg], b1 = bias[cg + 1];
                v0 += b0; v1 += b1; v2 += b0; v3 += b1;
            }
            if (EPI == 0) {
                v0 = tanhf(v0); v1 = tanhf(v1); v2 = tanhf(v2); v3 = tanhf(v3);
            }
            if (EPI == 2 || EPI == 3) {
                *(float2*)(Cf + (size_t)rg * Ntotal + cg)       = make_float2(v0, v1);
                *(float2*)(Cf + (size_t)(rg + 8) * Ntotal + cg) = make_float2(v2, v3);
            }
            if (EPI == 0 || EPI == 2) {
                *(__half2*)(Ch + (size_t)rg * Ntotal + cg)       = __floats2half2_rn(v0, v1);
                *(__half2*)(Ch + (size_t)(rg + 8) * Ntotal + cg) = __floats2half2_rn(v2, v3);
            }
        }
    }
}

// ---------------------------------------------------------------------------
// Fused logits + softmax (round-9 passing version, unchanged)
// ---------------------------------------------------------------------------
__global__ __launch_bounds__(256)
void logits_softmax(const __half* __restrict__ E,
                    const __half* __restrict__ MEMp,
                    float* __restrict__ att,
                    __half* __restrict__ AT)
{
    constexpr int A_BYTES = 10240, B_BYTES = 64 * 80;
    constexpr int OFF_A = 0, OFF_B = A_BYTES;
    constexpr int STAGE = A_BYTES + B_BYTES;           // 15360
    constexpr int OFF_LG = 2 * STAGE;                  // 30720

    extern __shared__ char smem[];
    const uint32_t sb = smem_u32(smem);
    const int tid = threadIdx.x, lane = tid & 31, wid = tid >> 5;
    const int wm = wid & 1, wn = wid >> 1;
    const int m0 = blockIdx.x * 128;

    float c[4][2][4];
#pragma unroll
    for (int mi = 0; mi < 4; mi++)
#pragma unroll
        for (int ni = 0; ni < 2; ni++)
#pragma unroll
            for (int j = 0; j < 4; j++) c[mi][ni][j] = 0.f;

    auto load_chunk = [&](int ch) {
        const uint32_t st = sb + (uint32_t)((ch & 1) * STAGE);
        const int kc = ch * 32;
#pragma unroll
        for (int i = 0; i < 2; i++) {
            int e = tid + i * 256;
            int r = e >> 2, g = e & 3;
            cp16(st + OFF_A + (uint32_t)(r * 80 + g * 16),
                 E + (size_t)(m0 + r) * D_K + kc + g * 8);
        }
        {
            int r = tid >> 2, g = tid & 3;
            if (r < 64)
                cp16(st + OFF_B + (uint32_t)(r * 80 + g * 16),
                     MEMp + (size_t)r * D_K + kc + g * 8);
        }
        cp_commit();
    };

    load_chunk(0);

    const uint32_t aRow = (uint32_t)((wm * 64 + (lane & 15)) * 80 + (lane >> 4) * 16);
    const uint32_t bRow = (uint32_t)((wn * 16 + (lane & 7)) * 80 + ((lane >> 3) & 1) * 16);

    for (int ch = 0; ch < 8; ch++) {
        cp_wait0();
        __syncthreads();
        if (ch + 1 < 8) load_chunk(ch + 1);

        const uint32_t st = sb + (uint32_t)((ch & 1) * STAGE);
#pragma unroll
        for (int kk = 0; kk < 2; kk++) {
            uint32_t a[4][4], b[2][2];
#pragma unroll
            for (int mi = 0; mi < 4; mi++) {
                uint32_t ad = st + OFF_A + aRow + (uint32_t)(mi * 1280 + kk * 32);
                LDSM4(a[mi][0], a[mi][1], a[mi][2], a[mi][3], ad);
            }
#pragma unroll
            for (int ni = 0; ni < 2; ni++) {
                uint32_t bd = st + OFF_B + bRow + (uint32_t)(ni * 640 + kk * 32);
                LDSM2(b[ni][0], b[ni][1], bd);
            }
#pragma unroll
            for (int mi = 0; mi < 4; mi++)
#pragma unroll
                for (int ni = 0; ni < 2; ni++)
                    MMA16816(c[mi][ni], a[mi], b[ni]);
        }
        __syncthreads();
    }

    float* LGf = (float*)(smem + OFF_LG);
    const int r_in = lane >> 2, cpair = (lane & 3) * 2;
#pragma unroll
    for (int mi = 0; mi < 4; mi++) {
        const int rl = wm * 64 + mi * 16 + r_in;
#pragma unroll
        for (int ni = 0; ni < 2; ni++) {
            const int cl = wn * 16 + ni * 8 + cpair;
            LGf[rl * 68 + cl]           = c[mi][ni][0] * 0.0625f;
            LGf[rl * 68 + cl + 1]       = c[mi][ni][1] * 0.0625f;
            LGf[(rl + 8) * 68 + cl]     = c[mi][ni][2] * 0.0625f;
            LGf[(rl + 8) * 68 + cl + 1] = c[mi][ni][3] * 0.0625f;
        }
    }
    __syncthreads();

    {
        const int row = tid >> 1, half = tid & 1;
        float* lr = LGf + row * 68 + half * 32;
        float mx = lr[0];
#pragma unroll 8
        for (int j = 1; j < 32; j++) mx = fmaxf(mx, lr[j]);
        mx = fmaxf(mx, __shfl_xor_sync(0xffffffffu, mx, 1));
        float sum = 0.f;
#pragma unroll 8
        for (int j = 0; j < 32; j++) {
            float p = expf(lr[j] - mx);
            lr[j] = p;
            sum += p;
        }
        sum += __shfl_xor_sync(0xffffffffu, sum, 1);
        float inv = 1.f / sum;
#pragma unroll 8
        for (int j = 0; j < 32; j++) lr[j] *= inv;
    }
    __syncthreads();

#pragma unroll
    for (int i = 0; i < 32; i++) {
        int idx = tid + i * 256;
        int r = idx >> 6, cc = idx & 63;
        float v = LGf[r * 68 + cc];
        att[(size_t)(m0 + r) * 64 + cc] = v;
        AT[(size_t)(m0 + r) * 64 + cc]  = __float2half_rn(v);
    }
}

// ---------------------------------------------------------------------------
// Conversions: big seq kernel + one merged weight kernel
// ---------------------------------------------------------------------------
__global__ void cvt_half4(const float4* __restrict__ x,
                          __half2* __restrict__ h, int n4)
{
    int i = blockIdx.x * blockDim.x + threadIdx.x;
    if (i >= n4) return;
    float4 v = x[i];
    h[2*i]   = __floats2half2_rn(v.x, v.y);
    h[2*i+1] = __floats2half2_rn(v.z, v.w);
}

// all weight conversions in one launch:
// region 0: enc_w (32768 float4) -> EW
// region 1: mem   (4096 float4)  -> MEM
// region 2: dec_w (32768 float4) -> DW
// region 3: mem transpose (16384 scalars) -> MT
__global__ void cvt_weights(const float* __restrict__ enc_w,
                            const float* __restrict__ mem,
                            const float* __restrict__ dec_w,
                            __half2* __restrict__ EW,
                            __half2* __restrict__ MEM2,
                            __half2* __restrict__ DW,
                            __half* __restrict__ MT)
{
    int i = blockIdx.x * blockDim.x + threadIdx.x;
    if (i < 32768) {
        float4 v = ((const float4*)enc_w)[i];
        EW[2*i]   = __floats2half2_rn(v.x, v.y);
        EW[2*i+1] = __floats2half2_rn(v.z, v.w);
    } else if (i < 32768 + 4096) {
        int j = i - 32768;
        float4 v = ((const float4*)mem)[j];
        MEM2[2*j]   = __floats2half2_rn(v.x, v.y);
        MEM2[2*j+1] = __floats2half2_rn(v.z, v.w);
    } else if (i < 32768 + 4096 + 32768) {
        int j = i - 32768 - 4096;
        float4 v = ((const float4*)dec_w)[j];
        DW[2*j]   = __floats2half2_rn(v.x, v.y);
        DW[2*j+1] = __floats2half2_rn(v.z, v.w);
    } else if (i < 32768 + 4096 + 32768 + 16384) {
        int j = i - 32768 - 4096 - 32768;       // j over mem [64][256]
        int r = j >> 8, cc = j & 255;
        MT[(size_t)cc * MSLOTS + r] = __float2half_rn(mem[j]);
    }
}

// ---------------------------------------------------------------------------
// launch
// ---------------------------------------------------------------------------
extern "C" void kernel_launch(void* const* d_in, const int* in_sizes, int n_in,
                              void* d_out, int out_size)
{
    const float* seq   = (const float*)d_in[0];
    const float* enc_w = (const float*)d_in[1];
    const float* enc_b = (const float*)d_in[2];
    const float* mem   = (const float*)d_in[3];
    const float* dec_w = (const float*)d_in[4];
    const float* dec_b = (const float*)d_in[5];

    float* out   = (float*)d_out;
    float* recon = out;
    float* att   = out + (size_t)NTOK * D_IN;
    float* memo  = att + (size_t)NTOK * MSLOTS;

    __half *S, *E, *AT, *M, *EW, *MEM, *MT, *DW;
    cudaGetSymbolAddress((void**)&S, g_S);
    cudaGetSymbolAddress((void**)&E, g_E);
    cudaGetSymbolAddress((void**)&AT, g_AT);
    cudaGetSymbolAddress((void**)&M, g_M);
    cudaGetSymbolAddress((void**)&EW, g_EW);
    cudaGetSymbolAddress((void**)&MEM, g_MEM);
    cudaGetSymbolAddress((void**)&MT, g_MT);
    cudaGetSymbolAddress((void**)&DW, g_DW);

    const int SM128 = 3 * (10240 + 128 * 80);          // 61440 (3 stages)
    const int SM_LS = 2 * (10240 + 64 * 80) + 34816;   // 65536
    cudaFuncSetAttribute(mma_gemm<128, 0>, cudaFuncAttributeMaxDynamicSharedMemorySize, SM128);
    cudaFuncSetAttribute(logits_softmax,   cudaFuncAttributeMaxDynamicSharedMemorySize, SM_LS);
    cudaFuncSetAttribute(mma_gemm<128, 2>, cudaFuncAttributeMaxDynamicSharedMemorySize, SM128);
    cudaFuncSetAttribute(mma_gemm<128, 3>, cudaFuncAttributeMaxDynamicSharedMemorySize, SM128);

    // conversions: 2 launches total
    {
        const int nW = 32768 + 4096 + 32768 + 16384;   // 86016
        cvt_weights<<<(nW + 255) / 256, 256>>>(enc_w, mem, dec_w,
                                               (__half2*)EW, (__half2*)MEM,
                                               (__half2*)DW, MT);
        int n4 = NTOK * D_IN / 4;
        cvt_half4<<<(n4 + 255) / 256, 256>>>((const float4*)seq, (__half2*)S, n4);
    }

    // 1) encoded = tanh(seq @ enc_w^T + enc_b) -> fp16
    {
        dim3 grid(D_K / 128, NTOK / 128);
        mma_gemm<128, 0><<<grid, 256, SM128>>>(S, EW, enc_b, nullptr, E,
                                               D_K, D_IN);
    }
    // 2) fused logits + softmax -> att fp32 (d_out) + AT fp16
    logits_softmax<<<NTOK / 128, 256, SM_LS>>>(E, MEM, att, AT);

    // 3) memory = att @ mem -> memo fp32 (d_out) + M fp16
    {
        dim3 grid(D_K / 128, NTOK / 128);
        mma_gemm<128, 2><<<grid, 256, SM128>>>(AT, MT, nullptr, memo, M,
                                               D_K, MSLOTS);
    }
    // 4) recon = M @ dec_w^T + dec_b -> fp32 (d_out)
    {
        dim3 grid(D_IN / 128, NTOK / 128);
        mma_gemm<128, 3><<<grid, 256, SM128>>>(M, DW, dec_b, recon, nullptr,
                                               D_IN, D_K);
    }
}

// round 11
// speedup vs baseline: 1.2734x; 1.1067x over previous
#include <cuda_runtime.h>
#include <cuda_fp16.h>
#include <stdint.h>
#include <math.h>

#define NTOK   (16 * 4096)   // 65536 tokens
#define D_IN   512
#define D_K    256
#define MSLOTS 64

// ---------------------------------------------------------------------------
// Scratch (fp16 representations)
// ---------------------------------------------------------------------------
__device__ __align__(256) __half g_E[(size_t)NTOK * D_K];     // encoded fp16
__device__ __align__(256) __half g_AT[(size_t)NTOK * MSLOTS]; // attention fp16
__device__ __align__(256) __half g_M[(size_t)NTOK * D_K];     // memory-read fp16
__device__ __align__(256) __half g_EW[D_K * D_IN];            // enc_w fp16
__device__ __align__(256) __half g_MEM[MSLOTS * D_K];         // mem fp16
__device__ __align__(256) __half g_MT[D_K * MSLOTS];          // mem^T fp16
__device__ __align__(256) __half g_DW[D_IN * D_K];            // dec_w fp16

// ---------------------------------------------------------------------------
// PTX helpers
// ---------------------------------------------------------------------------
__device__ __forceinline__ uint32_t smem_u32(const void* p) {
    uint32_t a;
    asm("{ .reg .u64 t; cvta.to.shared.u64 t, %1; cvt.u32.u64 %0, t; }"
        : "=r"(a) : "l"(p));
    return a;
}
__device__ __forceinline__ void cp16(uint32_t dst, const void* src) {
    asm volatile("cp.async.cg.shared.global [%0], [%1], 16;"
                 :: "r"(dst), "l"(src));
}
__device__ __forceinline__ void cp_commit() {
    asm volatile("cp.async.commit_group;");
}
__device__ __forceinline__ void cp_wait0() {
    asm volatile("cp.async.wait_group 0;" ::: "memory");
}
__device__ __forceinline__ void cp_wait1() {
    asm volatile("cp.async.wait_group 1;" ::: "memory");
}

#define LDSM4(r0, r1, r2, r3, addr)                                            \
    asm volatile("ldmatrix.sync.aligned.m8n8.x4.shared.b16 {%0,%1,%2,%3}, [%4];" \
                 : "=r"(r0), "=r"(r1), "=r"(r2), "=r"(r3) : "r"(addr))
#define LDSM2(r0, r1, addr)                                                    \
    asm volatile("ldmatrix.sync.aligned.m8n8.x2.shared.b16 {%0,%1}, [%2];"     \
                 : "=r"(r0), "=r"(r1) : "r"(addr))
#define MMA16816(c, a, b)                                                      \
    asm volatile(                                                              \
        "mma.sync.aligned.m16n8k16.row.col.f32.f16.f16.f32 "                   \
        "{%0,%1,%2,%3},{%4,%5,%6,%7},{%8,%9},{%0,%1,%2,%3};"                   \
        : "+f"((c)[0]), "+f"((c)[1]), "+f"((c)[2]), "+f"((c)[3])               \
        : "r"((a)[0]), "r"((a)[1]), "r"((a)[2]), "r"((a)[3]),                  \
          "r"((b)[0]), "r"((b)[1]))

// ---------------------------------------------------------------------------
// K1: encoded = tanh(seq @ enc_w^T + enc_b). seq read as fp32, converted
// in-kernel: cp.async fp32 A stage (pitch 144B) -> smem convert pass ->
// fp16 tile (pitch 80B) -> ldmatrix/MMA (unchanged template core).
// NT=128, K=512 (16 chunks), grid (2, 512). smem 66 KB, 2 CTAs/SM.
// ---------------------------------------------------------------------------
__global__ __launch_bounds__(256, 2)
void gemm_enc(const float* __restrict__ A,
              const __half* __restrict__ B,
              const float* __restrict__ bias,
              __half* __restrict__ E)
{
    constexpr int AF32_BYTES = 128 * 144;      // 18432 per stage
    constexpr int B_BYTES    = 128 * 80;       // 10240 per stage
    constexpr int OFF_AF = 0;                  // 2 x 18432
    constexpr int OFF_B  = 2 * AF32_BYTES;     // 2 x 10240
    constexpr int OFF_AH = OFF_B + 2 * B_BYTES;// 10240 (single buffer)

    extern __shared__ char smem[];
    const uint32_t sb = smem_u32(smem);
    const int tid = threadIdx.x, lane = tid & 31, wid = tid >> 5;
    const int wm = wid & 1, wn = wid >> 1;
    const int m0 = blockIdx.y * 128;
    const int n0 = blockIdx.x * 128;

    float c[4][4][4];
#pragma unroll
    for (int mi = 0; mi < 4; mi++)
#pragma unroll
        for (int ni = 0; ni < 4; ni++)
#pragma unroll
            for (int j = 0; j < 4; j++) c[mi][ni][j] = 0.f;

    auto load_chunk = [&](int ch) {
        const int kc = ch * 32;
        const uint32_t stA = sb + OFF_AF + (uint32_t)((ch & 1) * AF32_BYTES);
        const uint32_t stB = sb + OFF_B  + (uint32_t)((ch & 1) * B_BYTES);
        // A fp32: 128 rows x 8 granules of 16B
#pragma unroll
        for (int i = 0; i < 4; i++) {
            int e = tid + i * 256;
            int r = e >> 3, g = e & 7;
            cp16(stA + (uint32_t)(r * 144 + g * 16),
                 A + (size_t)(m0 + r) * D_IN + kc + g * 4);
        }
        // B fp16: 128 rows x 4 granules
#pragma unroll
        for (int i = 0; i < 2; i++) {
            int e = tid + i * 256;
            int r = e >> 2, g = e & 3;
            cp16(stB + (uint32_t)(r * 80 + g * 16),
                 B + (size_t)(n0 + r) * D_IN + kc + g * 8);
        }
        cp_commit();
    };

    load_chunk(0);

    const uint32_t aRow = (uint32_t)((wm * 64 + (lane & 15)) * 80 + (lane >> 4) * 16);
    const uint32_t bRow = (uint32_t)((wn * 32 + (lane & 7)) * 80 + ((lane >> 3) & 1) * 16);
    const int cr  = tid & 127;       // row for convert pass
    const int chf = tid >> 7;        // which 16-col half

    for (int ch = 0; ch < 16; ch++) {
        cp_wait0();
        __syncthreads();             // loads ch visible; MMA ch-1 done (AH free)

        // ---- convert fp32 stage -> fp16 tile (16 floats / thread)
        {
            const char* src = smem + OFF_AF + (ch & 1) * AF32_BYTES
                            + cr * 144 + chf * 64;
            float4 f0 = *(const float4*)(src);
            float4 f1 = *(const float4*)(src + 16);
            float4 f2 = *(const float4*)(src + 32);
            float4 f3 = *(const float4*)(src + 48);
            __half2 h[8];
            h[0] = __floats2half2_rn(f0.x, f0.y);
            h[1] = __floats2half2_rn(f0.z, f0.w);
            h[2] = __floats2half2_rn(f1.x, f1.y);
            h[3] = __floats2half2_rn(f1.z, f1.w);
            h[4] = __floats2half2_rn(f2.x, f2.y);
            h[5] = __floats2half2_rn(f2.z, f2.w);
            h[6] = __floats2half2_rn(f3.x, f3.y);
            h[7] = __floats2half2_rn(f3.z, f3.w);
            uint4* dst = (uint4*)(smem + OFF_AH + cr * 80 + chf * 32);
            uint4 u0, u1;
            u0.x = *(uint32_t*)&h[0]; u0.y = *(uint32_t*)&h[1];
            u0.z = *(uint32_t*)&h[2]; u0.w = *(uint32_t*)&h[3];
            u1.x = *(uint32_t*)&h[4]; u1.y = *(uint32_t*)&h[5];
            u1.z = *(uint32_t*)&h[6]; u1.w = *(uint32_t*)&h[7];
            dst[0] = u0; dst[1] = u1;
        }

        if (ch + 1 < 16) load_chunk(ch + 1);   // overlaps with convert/MMA
        __syncthreads();                       // fp16 tile visible

        const uint32_t stB = sb + OFF_B + (uint32_t)((ch & 1) * B_BYTES);
#pragma unroll
        for (int kk = 0; kk < 2; kk++) {
            uint32_t a[4][4], b[4][2];
#pragma unroll
            for (int mi = 0; mi < 4; mi++) {
                uint32_t ad = sb + OFF_AH + aRow + (uint32_t)(mi * 1280 + kk * 32);
                LDSM4(a[mi][0], a[mi][1], a[mi][2], a[mi][3], ad);
            }
#pragma unroll
            for (int ni = 0; ni < 4; ni++) {
                uint32_t bd = stB + bRow + (uint32_t)(ni * 640 + kk * 32);
                LDSM2(b[ni][0], b[ni][1], bd);
            }
#pragma unroll
            for (int mi = 0; mi < 4; mi++)
#pragma unroll
                for (int ni = 0; ni < 4; ni++)
                    MMA16816(c[mi][ni], a[mi], b[ni]);
        }
    }

    const int r_in = lane >> 2, cpair = (lane & 3) * 2;
#pragma unroll
    for (int mi = 0; mi < 4; mi++) {
        const int rg = m0 + wm * 64 + mi * 16 + r_in;
#pragma unroll
        for (int ni = 0; ni < 4; ni++) {
            const int cg = n0 + wn * 32 + ni * 8 + cpair;
            float b0 = bias[cg], b1 = bias[cg + 1];
            float v0 = tanhf(c[mi][ni][0] + b0);
            float v1 = tanhf(c[mi][ni][1] + b1);
            float v2 = tanhf(c[mi][ni][2] + b0);
            float v3 = tanhf(c[mi][ni][3] + b1);
            *(__half2*)(E + (size_t)rg * D_K + cg)       = __floats2half2_rn(v0, v1);
            *(__half2*)(E + (size_t)(rg + 8) * D_K + cg) = __floats2half2_rn(v2, v3);
        }
    }
}

// ---------------------------------------------------------------------------
// Generic fp16 GEMM, 3-stage cp.async pipeline (round-10 proven).
// EPI: 2 = identity, write fp32 (Cf) AND fp16 (Ch); 3 = +bias, write fp32.
// ---------------------------------------------------------------------------
template <int NT, int EPI>
__global__ __launch_bounds__(256, 2)
void mma_gemm(const __half* __restrict__ A,
              const __half* __restrict__ B,
              const float* __restrict__ bias,
              float* __restrict__ Cf,
              __half* __restrict__ Ch,
              int Ntotal, int K)
{
    constexpr int NW  = NT / 32;
    constexpr int NWC = NT / 4;
    constexpr int A_BYTES = 128 * 40 * 2;  // 10240
    constexpr int B_BYTES = NT * 40 * 2;
    constexpr int OFF_A = 0, OFF_B = A_BYTES;
    constexpr int STAGE = A_BYTES + B_BYTES;

    extern __shared__ char smem[];
    const uint32_t sb = smem_u32(smem);

    const int tid  = threadIdx.x;
    const int lane = tid & 31;
    const int wid  = tid >> 5;
    const int wm   = wid & 1;
    const int wn   = wid >> 1;
    const int m0   = blockIdx.y * 128;
    const int n0   = blockIdx.x * NT;

    float c[4][NW][4];
#pragma unroll
    for (int mi = 0; mi < 4; mi++)
#pragma unroll
        for (int ni = 0; ni < NW; ni++)
#pragma unroll
            for (int j = 0; j < 4; j++) c[mi][ni][j] = 0.f;

    const int nch = K >> 5;

    auto load_chunk = [&](int ch) {
        if (ch < nch) {
            const uint32_t st = sb + (uint32_t)((ch % 3) * STAGE);
            const int kc = ch * 32;
#pragma unroll
            for (int i = 0; i < 2; i++) {
                int e = tid + i * 256;
                int r = e >> 2, g = e & 3;
                cp16(st + OFF_A + (uint32_t)(r * 80 + g * 16),
                     A + (size_t)(m0 + r) * K + kc + g * 8);
            }
#pragma unroll
            for (int i = 0; i < NT / 64; i++) {
                int e = tid + i * 256;
                int r = e >> 2, g = e & 3;
                cp16(st + OFF_B + (uint32_t)(r * 80 + g * 16),
                     B + (size_t)(n0 + r) * K + kc + g * 8);
            }
        }
        cp_commit();
    };

    load_chunk(0);
    load_chunk(1);

    const uint32_t aRow = (uint32_t)((wm * 64 + (lane & 15)) * 80 + (lane >> 4) * 16);
    const uint32_t bRow = (uint32_t)((wn * NWC + (lane & 7)) * 80 + ((lane >> 3) & 1) * 16);

    for (int ch = 0; ch < nch; ch++) {
        cp_wait1();
        __syncthreads();
        load_chunk(ch + 2);

        const uint32_t st = sb + (uint32_t)((ch % 3) * STAGE);
#pragma unroll
        for (int kk = 0; kk < 2; kk++) {
            uint32_t a[4][4], b[NW][2];
#pragma unroll
            for (int mi = 0; mi < 4; mi++) {
                uint32_t ad = st + OFF_A + aRow + (uint32_t)(mi * 1280 + kk * 32);
                LDSM4(a[mi][0], a[mi][1], a[mi][2], a[mi][3], ad);
            }
#pragma unroll
            for (int ni = 0; ni < NW; ni++) {
                uint32_t bd = st + OFF_B + bRow + (uint32_t)(ni * 640 + kk * 32);
                LDSM2(b[ni][0], b[ni][1], bd);
            }
#pragma unroll
            for (int mi = 0; mi < 4; mi++)
#pragma unroll
                for (int ni = 0; ni < NW; ni++)
                    MMA16816(c[mi][ni], a[mi], b[ni]);
        }
    }

    const int r_in  = lane >> 2;
    const int cpair = (lane & 3) * 2;
#pragma unroll
    for (int mi = 0; mi < 4; mi++) {
        const int rg = m0 + wm * 64 + mi * 16 + r_in;
#pragma unroll
        for (int ni = 0; ni < NW; ni++) {
            const int cg = n0 + wn * NWC + ni * 8 + cpair;
            float v0 = c[mi][ni][0], v1 = c[mi][ni][1];
            float v2 = c[mi][ni][2], v3 = c[mi][ni][3];
            if (EPI == 3) {
                float b0 = bias[cg], b1 = bias[cg + 1];
                v0 += b0; v1 += b1; v2 += b0; v3 += b1;
            }
            *(float2*)(Cf + (size_t)rg * Ntotal + cg)       = make_float2(v0, v1);
            *(float2*)(Cf + (size_t)(rg + 8) * Ntotal + cg) = make_float2(v2, v3);
            if (EPI == 2) {
                *(__half2*)(Ch + (size_t)rg * Ntotal + cg)       = __floats2half2_rn(v0, v1);
                *(__half2*)(Ch + (size_t)(rg + 8) * Ntotal + cg) = __floats2half2_rn(v2, v3);
            }
        }
    }
}

// ---------------------------------------------------------------------------
// Fused logits + softmax (round-9/10 passing version, unchanged)
// ---------------------------------------------------------------------------
__global__ __launch_bounds__(256)
void logits_softmax(const __half* __restrict__ E,
                    const __half* __restrict__ MEMp,
                    float* __restrict__ att,
                    __half* __restrict__ AT)
{
    constexpr int A_BYTES = 10240, B_BYTES = 64 * 80;
    constexpr int OFF_A = 0, OFF_B = A_BYTES;
    constexpr int STAGE = A_BYTES + B_BYTES;           // 15360
    constexpr int OFF_LG = 2 * STAGE;                  // 30720

    extern __shared__ char smem[];
    const uint32_t sb = smem_u32(smem);
    const int tid = threadIdx.x, lane = tid & 31, wid = tid >> 5;
    const int wm = wid & 1, wn = wid >> 1;
    const int m0 = blockIdx.x * 128;

    float c[4][2][4];
#pragma unroll
    for (int mi = 0; mi < 4; mi++)
#pragma unroll
        for (int ni = 0; ni < 2; ni++)
#pragma unroll
            for (int j = 0; j < 4; j++) c[mi][ni][j] = 0.f;

    auto load_chunk = [&](int ch) {
        const uint32_t st = sb + (uint32_t)((ch & 1) * STAGE);
        const int kc = ch * 32;
#pragma unroll
        for (int i = 0; i < 2; i++) {
            int e = tid + i * 256;
            int r = e >> 2, g = e & 3;
            cp16(st + OFF_A + (uint32_t)(r * 80 + g * 16),
                 E + (size_t)(m0 + r) * D_K + kc + g * 8);
        }
        {
            int r = tid >> 2, g = tid & 3;
            if (r < 64)
                cp16(st + OFF_B + (uint32_t)(r * 80 + g * 16),
                     MEMp + (size_t)r * D_K + kc + g * 8);
        }
        cp_commit();
    };

    load_chunk(0);

    const uint32_t aRow = (uint32_t)((wm * 64 + (lane & 15)) * 80 + (lane >> 4) * 16);
    const uint32_t bRow = (uint32_t)((wn * 16 + (lane & 7)) * 80 + ((lane >> 3) & 1) * 16);

    for (int ch = 0; ch < 8; ch++) {
        cp_wait0();
        __syncthreads();
        if (ch + 1 < 8) load_chunk(ch + 1);

        const uint32_t st = sb + (uint32_t)((ch & 1) * STAGE);
#pragma unroll
        for (int kk = 0; kk < 2; kk++) {
            uint32_t a[4][4], b[2][2];
#pragma unroll
            for (int mi = 0; mi < 4; mi++) {
                uint32_t ad = st + OFF_A + aRow + (uint32_t)(mi * 1280 + kk * 32);
                LDSM4(a[mi][0], a[mi][1], a[mi][2], a[mi][3], ad);
            }
#pragma unroll
            for (int ni = 0; ni < 2; ni++) {
                uint32_t bd = st + OFF_B + bRow + (uint32_t)(ni * 640 + kk * 32);
                LDSM2(b[ni][0], b[ni][1], bd);
            }
#pragma unroll
            for (int mi = 0; mi < 4; mi++)
#pragma unroll
                for (int ni = 0; ni < 2; ni++)
                    MMA16816(c[mi][ni], a[mi], b[ni]);
        }
        __syncthreads();
    }

    float* LGf = (float*)(smem + OFF_LG);
    const int r_in = lane >> 2, cpair = (lane & 3) * 2;
#pragma unroll
    for (int mi = 0; mi < 4; mi++) {
        const int rl = wm * 64 + mi * 16 + r_in;
#pragma unroll
        for (int ni = 0; ni < 2; ni++) {
            const int cl = wn * 16 + ni * 8 + cpair;
            LGf[rl * 68 + cl]           = c[mi][ni][0] * 0.0625f;
            LGf[rl * 68 + cl + 1]       = c[mi][ni][1] * 0.0625f;
            LGf[(rl + 8) * 68 + cl]     = c[mi][ni][2] * 0.0625f;
            LGf[(rl + 8) * 68 + cl + 1] = c[mi][ni][3] * 0.0625f;
        }
    }
    __syncthreads();

    {
        const int row = tid >> 1, half = tid & 1;
        float* lr = LGf + row * 68 + half * 32;
        float mx = lr[0];
#pragma unroll 8
        for (int j = 1; j < 32; j++) mx = fmaxf(mx, lr[j]);
        mx = fmaxf(mx, __shfl_xor_sync(0xffffffffu, mx, 1));
        float sum = 0.f;
#pragma unroll 8
        for (int j = 0; j < 32; j++) {
            float p = expf(lr[j] - mx);
            lr[j] = p;
            sum += p;
        }
        sum += __shfl_xor_sync(0xffffffffu, sum, 1);
        float inv = 1.f / sum;
#pragma unroll 8
        for (int j = 0; j < 32; j++) lr[j] *= inv;
    }
    __syncthreads();

#pragma unroll
    for (int i = 0; i < 32; i++) {
        int idx = tid + i * 256;
        int r = idx >> 6, cc = idx & 63;
        float v = LGf[r * 68 + cc];
        att[(size_t)(m0 + r) * 64 + cc] = v;
        AT[(size_t)(m0 + r) * 64 + cc]  = __float2half_rn(v);
    }
}

// ---------------------------------------------------------------------------
// One merged weight-conversion kernel
// ---------------------------------------------------------------------------
__global__ void cvt_weights(const float* __restrict__ enc_w,
                            const float* __restrict__ mem,
                            const float* __restrict__ dec_w,
                            __half2* __restrict__ EW,
                            __half2* __restrict__ MEM2,
                            __half2* __restrict__ DW,
                            __half* __restrict__ MT)
{
    int i = blockIdx.x * blockDim.x + threadIdx.x;
    if (i < 32768) {
        float4 v = ((const float4*)enc_w)[i];
        EW[2*i]   = __floats2half2_rn(v.x, v.y);
        EW[2*i+1] = __floats2half2_rn(v.z, v.w);
    } else if (i < 32768 + 4096) {
        int j = i - 32768;
        float4 v = ((const float4*)mem)[j];
        MEM2[2*j]   = __floats2half2_rn(v.x, v.y);
        MEM2[2*j+1] = __floats2half2_rn(v.z, v.w);
    } else if (i < 32768 + 4096 + 32768) {
        int j = i - 32768 - 4096;
        float4 v = ((const float4*)dec_w)[j];
        DW[2*j]   = __floats2half2_rn(v.x, v.y);
        DW[2*j+1] = __floats2half2_rn(v.z, v.w);
    } else if (i < 32768 + 4096 + 32768 + 16384) {
        int j = i - 32768 - 4096 - 32768;
        int r = j >> 8, cc = j & 255;
        MT[(size_t)cc * MSLOTS + r] = __float2half_rn(mem[j]);
    }
}

// ---------------------------------------------------------------------------
// launch
// ---------------------------------------------------------------------------
extern "C" void kernel_launch(void* const* d_in, const int* in_sizes, int n_in,
                              void* d_out, int out_size)
{
    const float* seq   = (const float*)d_in[0];
    const float* enc_w = (const float*)d_in[1];
    const float* enc_b = (const float*)d_in[2];
    const float* mem   = (const float*)d_in[3];
    const float* dec_w = (const float*)d_in[4];
    const float* dec_b = (const float*)d_in[5];

    float* out   = (float*)d_out;
    float* recon = out;
    float* att   = out + (size_t)NTOK * D_IN;
    float* memo  = att + (size_t)NTOK * MSLOTS;

    __half *E, *AT, *M, *EW, *MEM, *MT, *DW;
    cudaGetSymbolAddress((void**)&E, g_E);
    cudaGetSymbolAddress((void**)&AT, g_AT);
    cudaGetSymbolAddress((void**)&M, g_M);
    cudaGetSymbolAddress((void**)&EW, g_EW);
    cudaGetSymbolAddress((void**)&MEM, g_MEM);
    cudaGetSymbolAddress((void**)&MT, g_MT);
    cudaGetSymbolAddress((void**)&DW, g_DW);

    const int SM_G1 = 2 * 18432 + 2 * 10240 + 10240;   // 67584
    const int SM128 = 3 * (10240 + 128 * 80);          // 61440
    const int SM_LS = 2 * (10240 + 64 * 80) + 34816;   // 65536
    cudaFuncSetAttribute(gemm_enc,         cudaFuncAttributeMaxDynamicSharedMemorySize, SM_G1);
    cudaFuncSetAttribute(logits_softmax,   cudaFuncAttributeMaxDynamicSharedMemorySize, SM_LS);
    cudaFuncSetAttribute(mma_gemm<128, 2>, cudaFuncAttributeMaxDynamicSharedMemorySize, SM128);
    cudaFuncSetAttribute(mma_gemm<128, 3>, cudaFuncAttributeMaxDynamicSharedMemorySize, SM128);

    // weight conversions (one launch)
    {
        const int nW = 32768 + 4096 + 32768 + 16384;   // 86016
        cvt_weights<<<(nW + 255) / 256, 256>>>(enc_w, mem, dec_w,
                                               (__half2*)EW, (__half2*)MEM,
                                               (__half2*)DW, MT);
    }

    // 1) encoded = tanh(seq @ enc_w^T + enc_b) -> fp16 (seq converted inline)
    {
        dim3 grid(D_K / 128, NTOK / 128);
        gemm_enc<<<grid, 256, SM_G1>>>(seq, EW, enc_b, E);
    }
    // 2) fused logits + softmax -> att fp32 (d_out) + AT fp16
    logits_softmax<<<NTOK / 128, 256, SM_LS>>>(E, MEM, att, AT);

    // 3) memory = att @ mem -> memo fp32 (d_out) + M fp16
    {
        dim3 grid(D_K / 128, NTOK / 128);
        mma_gemm<128, 2><<<grid, 256, SM128>>>(AT, MT, nullptr, memo, M,
                                               D_K, MSLOTS);
    }
    // 4) recon = M @ dec_w^T + dec_b -> fp32 (d_out)
    {
        dim3 grid(D_IN / 128, NTOK / 128);
        mma_gemm<128, 3><<<grid, 256, SM128>>>(M, DW, dec_b, recon, nullptr,
                                               D_IN, D_K);
    }
}

// round 12
// speedup vs baseline: 1.3325x; 1.0464x over previous
#include <cuda_runtime.h>
#include <cuda_fp16.h>
#include <stdint.h>
#include <math.h>

#define NTOK   (16 * 4096)   // 65536 tokens
#define D_IN   512
#define D_K    256
#define MSLOTS 64

// ---------------------------------------------------------------------------
// Scratch (fp16 representations)
// ---------------------------------------------------------------------------
__device__ __align__(256) __half g_E[(size_t)NTOK * D_K];     // encoded fp16
__device__ __align__(256) __half g_AT[(size_t)NTOK * MSLOTS]; // attention fp16
__device__ __align__(256) __half g_M[(size_t)NTOK * D_K];     // memory-read fp16
__device__ __align__(256) __half g_EW[D_K * D_IN];            // enc_w fp16
__device__ __align__(256) __half g_MEM[MSLOTS * D_K];         // mem fp16
__device__ __align__(256) __half g_MT[D_K * MSLOTS];          // mem^T fp16
__device__ __align__(256) __half g_DW[D_IN * D_K];            // dec_w fp16

// ---------------------------------------------------------------------------
// PTX helpers
// ---------------------------------------------------------------------------
__device__ __forceinline__ uint32_t smem_u32(const void* p) {
    uint32_t a;
    asm("{ .reg .u64 t; cvta.to.shared.u64 t, %1; cvt.u32.u64 %0, t; }"
        : "=r"(a) : "l"(p));
    return a;
}
__device__ __forceinline__ void cp16(uint32_t dst, const void* src) {
    asm volatile("cp.async.cg.shared.global [%0], [%1], 16;"
                 :: "r"(dst), "l"(src));
}
__device__ __forceinline__ void cp_commit() {
    asm volatile("cp.async.commit_group;");
}
__device__ __forceinline__ void cp_wait0() {
    asm volatile("cp.async.wait_group 0;" ::: "memory");
}
__device__ __forceinline__ void cp_wait1() {
    asm volatile("cp.async.wait_group 1;" ::: "memory");
}

#define LDSM4(r0, r1, r2, r3, addr)                                            \
    asm volatile("ldmatrix.sync.aligned.m8n8.x4.shared.b16 {%0,%1,%2,%3}, [%4];" \
                 : "=r"(r0), "=r"(r1), "=r"(r2), "=r"(r3) : "r"(addr))
#define LDSM2(r0, r1, addr)                                                    \
    asm volatile("ldmatrix.sync.aligned.m8n8.x2.shared.b16 {%0,%1}, [%2];"     \
                 : "=r"(r0), "=r"(r1) : "r"(addr))
#define MMA16816(c, a, b)                                                      \
    asm volatile(                                                              \
        "mma.sync.aligned.m16n8k16.row.col.f32.f16.f16.f32 "                   \
        "{%0,%1,%2,%3},{%4,%5,%6,%7},{%8,%9},{%0,%1,%2,%3};"                   \
        : "+f"((c)[0]), "+f"((c)[1]), "+f"((c)[2]), "+f"((c)[3])               \
        : "r"((a)[0]), "r"((a)[1]), "r"((a)[2]), "r"((a)[3]),                  \
          "r"((b)[0]), "r"((b)[1]))

// ---------------------------------------------------------------------------
// K1: encoded = tanh(seq @ enc_w^T + enc_b). seq fp32 converted in-kernel.
// (round-11 passing version, unchanged)
// ---------------------------------------------------------------------------
__global__ __launch_bounds__(256, 2)
void gemm_enc(const float* __restrict__ A,
              const __half* __restrict__ B,
              const float* __restrict__ bias,
              __half* __restrict__ E)
{
    constexpr int AF32_BYTES = 128 * 144;      // 18432 per stage
    constexpr int B_BYTES    = 128 * 80;       // 10240 per stage
    constexpr int OFF_AF = 0;
    constexpr int OFF_B  = 2 * AF32_BYTES;
    constexpr int OFF_AH = OFF_B + 2 * B_BYTES;

    extern __shared__ char smem[];
    const uint32_t sb = smem_u32(smem);
    const int tid = threadIdx.x, lane = tid & 31, wid = tid >> 5;
    const int wm = wid & 1, wn = wid >> 1;
    const int m0 = blockIdx.y * 128;
    const int n0 = blockIdx.x * 128;

    float c[4][4][4];
#pragma unroll
    for (int mi = 0; mi < 4; mi++)
#pragma unroll
        for (int ni = 0; ni < 4; ni++)
#pragma unroll
            for (int j = 0; j < 4; j++) c[mi][ni][j] = 0.f;

    auto load_chunk = [&](int ch) {
        const int kc = ch * 32;
        const uint32_t stA = sb + OFF_AF + (uint32_t)((ch & 1) * AF32_BYTES);
        const uint32_t stB = sb + OFF_B  + (uint32_t)((ch & 1) * B_BYTES);
#pragma unroll
        for (int i = 0; i < 4; i++) {
            int e = tid + i * 256;
            int r = e >> 3, g = e & 7;
            cp16(stA + (uint32_t)(r * 144 + g * 16),
                 A + (size_t)(m0 + r) * D_IN + kc + g * 4);
        }
#pragma unroll
        for (int i = 0; i < 2; i++) {
            int e = tid + i * 256;
            int r = e >> 2, g = e & 3;
            cp16(stB + (uint32_t)(r * 80 + g * 16),
                 B + (size_t)(n0 + r) * D_IN + kc + g * 8);
        }
        cp_commit();
    };

    load_chunk(0);

    const uint32_t aRow = (uint32_t)((wm * 64 + (lane & 15)) * 80 + (lane >> 4) * 16);
    const uint32_t bRow = (uint32_t)((wn * 32 + (lane & 7)) * 80 + ((lane >> 3) & 1) * 16);
    const int cr  = tid & 127;
    const int chf = tid >> 7;

    for (int ch = 0; ch < 16; ch++) {
        cp_wait0();
        __syncthreads();

        {
            const char* src = smem + OFF_AF + (ch & 1) * AF32_BYTES
                            + cr * 144 + chf * 64;
            float4 f0 = *(const float4*)(src);
            float4 f1 = *(const float4*)(src + 16);
            float4 f2 = *(const float4*)(src + 32);
            float4 f3 = *(const float4*)(src + 48);
            __half2 h[8];
            h[0] = __floats2half2_rn(f0.x, f0.y);
            h[1] = __floats2half2_rn(f0.z, f0.w);
            h[2] = __floats2half2_rn(f1.x, f1.y);
            h[3] = __floats2half2_rn(f1.z, f1.w);
            h[4] = __floats2half2_rn(f2.x, f2.y);
            h[5] = __floats2half2_rn(f2.z, f2.w);
            h[6] = __floats2half2_rn(f3.x, f3.y);
            h[7] = __floats2half2_rn(f3.z, f3.w);
            uint4* dst = (uint4*)(smem + OFF_AH + cr * 80 + chf * 32);
            uint4 u0, u1;
            u0.x = *(uint32_t*)&h[0]; u0.y = *(uint32_t*)&h[1];
            u0.z = *(uint32_t*)&h[2]; u0.w = *(uint32_t*)&h[3];
            u1.x = *(uint32_t*)&h[4]; u1.y = *(uint32_t*)&h[5];
            u1.z = *(uint32_t*)&h[6]; u1.w = *(uint32_t*)&h[7];
            dst[0] = u0; dst[1] = u1;
        }

        if (ch + 1 < 16) load_chunk(ch + 1);
        __syncthreads();

        const uint32_t stB = sb + OFF_B + (uint32_t)((ch & 1) * B_BYTES);
#pragma unroll
        for (int kk = 0; kk < 2; kk++) {
            uint32_t a[4][4], b[4][2];
#pragma unroll
            for (int mi = 0; mi < 4; mi++) {
                uint32_t ad = sb + OFF_AH + aRow + (uint32_t)(mi * 1280 + kk * 32);
                LDSM4(a[mi][0], a[mi][1], a[mi][2], a[mi][3], ad);
            }
#pragma unroll
            for (int ni = 0; ni < 4; ni++) {
                uint32_t bd = stB + bRow + (uint32_t)(ni * 640 + kk * 32);
                LDSM2(b[ni][0], b[ni][1], bd);
            }
#pragma unroll
            for (int mi = 0; mi < 4; mi++)
#pragma unroll
                for (int ni = 0; ni < 4; ni++)
                    MMA16816(c[mi][ni], a[mi], b[ni]);
        }
    }

    const int r_in = lane >> 2, cpair = (lane & 3) * 2;
#pragma unroll
    for (int mi = 0; mi < 4; mi++) {
        const int rg = m0 + wm * 64 + mi * 16 + r_in;
#pragma unroll
        for (int ni = 0; ni < 4; ni++) {
            const int cg = n0 + wn * 32 + ni * 8 + cpair;
            float b0 = bias[cg], b1 = bias[cg + 1];
            float v0 = tanhf(c[mi][ni][0] + b0);
            float v1 = tanhf(c[mi][ni][1] + b1);
            float v2 = tanhf(c[mi][ni][2] + b0);
            float v3 = tanhf(c[mi][ni][3] + b1);
            *(__half2*)(E + (size_t)rg * D_K + cg)       = __floats2half2_rn(v0, v1);
            *(__half2*)(E + (size_t)(rg + 8) * D_K + cg) = __floats2half2_rn(v2, v3);
        }
    }
}

// ---------------------------------------------------------------------------
// Generic fp16 GEMM, BK=64, 3-stage cp.async pipeline. Pitch 144B/row
// (64 halfs + 16B pad; 144/4=36==4 mod 32 -> 8-row ldmatrix covers all banks).
// EPI: 2 = identity, write fp32 (Cf) AND fp16 (Ch); 3 = +bias, write fp32.
// ---------------------------------------------------------------------------
template <int NT, int EPI>
__global__ __launch_bounds__(256, 2)
void mma_gemm(const __half* __restrict__ A,
              const __half* __restrict__ B,
              const float* __restrict__ bias,
              float* __restrict__ Cf,
              __half* __restrict__ Ch,
              int Ntotal, int K)
{
    constexpr int NW  = NT / 32;
    constexpr int NWC = NT / 4;
    constexpr int A_BYTES = 128 * 144;     // 18432
    constexpr int B_BYTES = NT * 144;
    constexpr int OFF_A = 0, OFF_B = A_BYTES;
    constexpr int STAGE = A_BYTES + B_BYTES;

    extern __shared__ char smem[];
    const uint32_t sb = smem_u32(smem);

    const int tid  = threadIdx.x;
    const int lane = tid & 31;
    const int wid  = tid >> 5;
    const int wm   = wid & 1;
    const int wn   = wid >> 1;
    const int m0   = blockIdx.y * 128;
    const int n0   = blockIdx.x * NT;

    float c[4][NW][4];
#pragma unroll
    for (int mi = 0; mi < 4; mi++)
#pragma unroll
        for (int ni = 0; ni < NW; ni++)
#pragma unroll
            for (int j = 0; j < 4; j++) c[mi][ni][j] = 0.f;

    const int nch = K >> 6;                // BK = 64

    auto load_chunk = [&](int ch) {
        if (ch < nch) {
            const uint32_t st = sb + (uint32_t)((ch % 3) * STAGE);
            const int kc = ch * 64;
#pragma unroll
            for (int i = 0; i < 4; i++) {
                int e = tid + i * 256;
                int r = e >> 3, g = e & 7;
                cp16(st + OFF_A + (uint32_t)(r * 144 + g * 16),
                     A + (size_t)(m0 + r) * K + kc + g * 8);
            }
#pragma unroll
            for (int i = 0; i < NT / 32; i++) {
                int e = tid + i * 256;
                int r = e >> 3, g = e & 7;
                cp16(st + OFF_B + (uint32_t)(r * 144 + g * 16),
                     B + (size_t)(n0 + r) * K + kc + g * 8);
            }
        }
        cp_commit();
    };

    load_chunk(0);
    load_chunk(1);

    const uint32_t aRow = (uint32_t)((wm * 64 + (lane & 15)) * 144 + (lane >> 4) * 16);
    const uint32_t bRow = (uint32_t)((wn * NWC + (lane & 7)) * 144 + ((lane >> 3) & 1) * 16);

    for (int ch = 0; ch < nch; ch++) {
        cp_wait1();
        __syncthreads();
        load_chunk(ch + 2);

        const uint32_t st = sb + (uint32_t)((ch % 3) * STAGE);
#pragma unroll
        for (int kk = 0; kk < 4; kk++) {   // four k16 steps in BK=64
            uint32_t a[4][4], b[NW][2];
#pragma unroll
            for (int mi = 0; mi < 4; mi++) {
                uint32_t ad = st + OFF_A + aRow + (uint32_t)(mi * 2304 + kk * 32);
                LDSM4(a[mi][0], a[mi][1], a[mi][2], a[mi][3], ad);
            }
#pragma unroll
            for (int ni = 0; ni < NW; ni++) {
                uint32_t bd = st + OFF_B + bRow + (uint32_t)(ni * 1152 + kk * 32);
                LDSM2(b[ni][0], b[ni][1], bd);
            }
#pragma unroll
            for (int mi = 0; mi < 4; mi++)
#pragma unroll
                for (int ni = 0; ni < NW; ni++)
                    MMA16816(c[mi][ni], a[mi], b[ni]);
        }
    }

    const int r_in  = lane >> 2;
    const int cpair = (lane & 3) * 2;
#pragma unroll
    for (int mi = 0; mi < 4; mi++) {
        const int rg = m0 + wm * 64 + mi * 16 + r_in;
#pragma unroll
        for (int ni = 0; ni < NW; ni++) {
            const int cg = n0 + wn * NWC + ni * 8 + cpair;
            float v0 = c[mi][ni][0], v1 = c[mi][ni][1];
            float v2 = c[mi][ni][2], v3 = c[mi][ni][3];
            if (EPI == 3) {
                float b0 = bias[cg], b1 = bias[cg + 1];
                v0 += b0; v1 += b1; v2 += b0; v3 += b1;
            }
            *(float2*)(Cf + (size_t)rg * Ntotal + cg)       = make_float2(v0, v1);
            *(float2*)(Cf + (size_t)(rg + 8) * Ntotal + cg) = make_float2(v2, v3);
            if (EPI == 2) {
                *(__half2*)(Ch + (size_t)rg * Ntotal + cg)       = __floats2half2_rn(v0, v1);
                *(__half2*)(Ch + (size_t)(rg + 8) * Ntotal + cg) = __floats2half2_rn(v2, v3);
            }
        }
    }
}

// ---------------------------------------------------------------------------
// Fused logits + softmax (round-10/11 passing version, unchanged)
// ---------------------------------------------------------------------------
__global__ __launch_bounds__(256)
void logits_softmax(const __half* __restrict__ E,
                    const __half* __restrict__ MEMp,
                    float* __restrict__ att,
                    __half* __restrict__ AT)
{
    constexpr int A_BYTES = 10240, B_BYTES = 64 * 80;
    constexpr int OFF_A = 0, OFF_B = A_BYTES;
    constexpr int STAGE = A_BYTES + B_BYTES;           // 15360
    constexpr int OFF_LG = 2 * STAGE;                  // 30720

    extern __shared__ char smem[];
    const uint32_t sb = smem_u32(smem);
    const int tid = threadIdx.x, lane = tid & 31, wid = tid >> 5;
    const int wm = wid & 1, wn = wid >> 1;
    const int m0 = blockIdx.x * 128;

    float c[4][2][4];
#pragma unroll
    for (int mi = 0; mi < 4; mi++)
#pragma unroll
        for (int ni = 0; ni < 2; ni++)
#pragma unroll
            for (int j = 0; j < 4; j++) c[mi][ni][j] = 0.f;

    auto load_chunk = [&](int ch) {
        const uint32_t st = sb + (uint32_t)((ch & 1) * STAGE);
        const int kc = ch * 32;
#pragma unroll
        for (int i = 0; i < 2; i++) {
            int e = tid + i * 256;
            int r = e >> 2, g = e & 3;
            cp16(st + OFF_A + (uint32_t)(r * 80 + g * 16),
                 E + (size_t)(m0 + r) * D_K + kc + g * 8);
        }
        {
            int r = tid >> 2, g = tid & 3;
            if (r < 64)
                cp16(st + OFF_B + (uint32_t)(r * 80 + g * 16),
                     MEMp + (size_t)r * D_K + kc + g * 8);
        }
        cp_commit();
    };

    load_chunk(0);

    const uint32_t aRow = (uint32_t)((wm * 64 + (lane & 15)) * 80 + (lane >> 4) * 16);
    const uint32_t bRow = (uint32_t)((wn * 16 + (lane & 7)) * 80 + ((lane >> 3) & 1) * 16);

    for (int ch = 0; ch < 8; ch++) {
        cp_wait0();
        __syncthreads();
        if (ch + 1 < 8) load_chunk(ch + 1);

        const uint32_t st = sb + (uint32_t)((ch & 1) * STAGE);
#pragma unroll
        for (int kk = 0; kk < 2; kk++) {
            uint32_t a[4][4], b[2][2];
#pragma unroll
            for (int mi = 0; mi < 4; mi++) {
                uint32_t ad = st + OFF_A + aRow + (uint32_t)(mi * 1280 + kk * 32);
                LDSM4(a[mi][0], a[mi][1], a[mi][2], a[mi][3], ad);
            }
#pragma unroll
            for (int ni = 0; ni < 2; ni++) {
                uint32_t bd = st + OFF_B + bRow + (uint32_t)(ni * 640 + kk * 32);
                LDSM2(b[ni][0], b[ni][1], bd);
            }
#pragma unroll
            for (int mi = 0; mi < 4; mi++)
#pragma unroll
                for (int ni = 0; ni < 2; ni++)
                    MMA16816(c[mi][ni], a[mi], b[ni]);
        }
        __syncthreads();
    }

    float* LGf = (float*)(smem + OFF_LG);
    const int r_in = lane >> 2, cpair = (lane & 3) * 2;
#pragma unroll
    for (int mi = 0; mi < 4; mi++) {
        const int rl = wm * 64 + mi * 16 + r_in;
#pragma unroll
        for (int ni = 0; ni < 2; ni++) {
            const int cl = wn * 16 + ni * 8 + cpair;
            LGf[rl * 68 + cl]           = c[mi][ni][0] * 0.0625f;
            LGf[rl * 68 + cl + 1]       = c[mi][ni][1] * 0.0625f;
            LGf[(rl + 8) * 68 + cl]     = c[mi][ni][2] * 0.0625f;
            LGf[(rl + 8) * 68 + cl + 1] = c[mi][ni][3] * 0.0625f;
        }
    }
    __syncthreads();

    {
        const int row = tid >> 1, half = tid & 1;
        float* lr = LGf + row * 68 + half * 32;
        float mx = lr[0];
#pragma unroll 8
        for (int j = 1; j < 32; j++) mx = fmaxf(mx, lr[j]);
        mx = fmaxf(mx, __shfl_xor_sync(0xffffffffu, mx, 1));
        float sum = 0.f;
#pragma unroll 8
        for (int j = 0; j < 32; j++) {
            float p = expf(lr[j] - mx);
            lr[j] = p;
            sum += p;
        }
        sum += __shfl_xor_sync(0xffffffffu, sum, 1);
        float inv = 1.f / sum;
#pragma unroll 8
        for (int j = 0; j < 32; j++) lr[j] *= inv;
    }
    __syncthreads();

#pragma unroll
    for (int i = 0; i < 32; i++) {
        int idx = tid + i * 256;
        int r = idx >> 6, cc = idx & 63;
        float v = LGf[r * 68 + cc];
        att[(size_t)(m0 + r) * 64 + cc] = v;
        AT[(size_t)(m0 + r) * 64 + cc]  = __float2half_rn(v);
    }
}

// ---------------------------------------------------------------------------
// One merged weight-conversion kernel
// ---------------------------------------------------------------------------
__global__ void cvt_weights(const float* __restrict__ enc_w,
                            const float* __restrict__ mem,
                            const float* __restrict__ dec_w,
                            __half2* __restrict__ EW,
                            __half2* __restrict__ MEM2,
                            __half2* __restrict__ DW,
                            __half* __restrict__ MT)
{
    int i = blockIdx.x * blockDim.x + threadIdx.x;
    if (i < 32768) {
        float4 v = ((const float4*)enc_w)[i];
        EW[2*i]   = __floats2half2_rn(v.x, v.y);
        EW[2*i+1] = __floats2half2_rn(v.z, v.w);
    } else if (i < 32768 + 4096) {
        int j = i - 32768;
        float4 v = ((const float4*)mem)[j];
        MEM2[2*j]   = __floats2half2_rn(v.x, v.y);
        MEM2[2*j+1] = __floats2half2_rn(v.z, v.w);
    } else if (i < 32768 + 4096 + 32768) {
        int j = i - 32768 - 4096;
        float4 v = ((const float4*)dec_w)[j];
        DW[2*j]   = __floats2half2_rn(v.x, v.y);
        DW[2*j+1] = __floats2half2_rn(v.z, v.w);
    } else if (i < 32768 + 4096 + 32768 + 16384) {
        int j = i - 32768 - 4096 - 32768;
        int r = j >> 8, cc = j & 255;
        MT[(size_t)cc * MSLOTS + r] = __float2half_rn(mem[j]);
    }
}

// ---------------------------------------------------------------------------
// launch
// ---------------------------------------------------------------------------
extern "C" void kernel_launch(void* const* d_in, const int* in_sizes, int n_in,
                              void* d_out, int out_size)
{
    const float* seq   = (const float*)d_in[0];
    const float* enc_w = (const float*)d_in[1];
    const float* enc_b = (const float*)d_in[2];
    const float* mem   = (const float*)d_in[3];
    const float* dec_w = (const float*)d_in[4];
    const float* dec_b = (const float*)d_in[5];

    float* out   = (float*)d_out;
    float* recon = out;
    float* att   = out + (size_t)NTOK * D_IN;
    float* memo  = att + (size_t)NTOK * MSLOTS;

    __half *E, *AT, *M, *EW, *MEM, *MT, *DW;
    cudaGetSymbolAddress((void**)&E, g_E);
    cudaGetSymbolAddress((void**)&AT, g_AT);
    cudaGetSymbolAddress((void**)&M, g_M);
    cudaGetSymbolAddress((void**)&EW, g_EW);
    cudaGetSymbolAddress((void**)&MEM, g_MEM);
    cudaGetSymbolAddress((void**)&MT, g_MT);
    cudaGetSymbolAddress((void**)&DW, g_DW);

    const int SM_G1   = 2 * 18432 + 2 * 10240 + 10240;   // 67584
    const int SM128K  = 3 * (18432 + 128 * 144);         // 110592 (BK=64)
    const int SM_LS   = 2 * (10240 + 64 * 80) + 34816;   // 65536
    cudaFuncSetAttribute(gemm_enc,         cudaFuncAttributeMaxDynamicSharedMemorySize, SM_G1);
    cudaFuncSetAttribute(logits_softmax,   cudaFuncAttributeMaxDynamicSharedMemorySize, SM_LS);
    cudaFuncSetAttribute(mma_gemm<128, 2>, cudaFuncAttributeMaxDynamicSharedMemorySize, SM128K);
    cudaFuncSetAttribute(mma_gemm<128, 3>, cudaFuncAttributeMaxDynamicSharedMemorySize, SM128K);

    // weight conversions (one launch)
    {
        const int nW = 32768 + 4096 + 32768 + 16384;
        cvt_weights<<<(nW + 255) / 256, 256>>>(enc_w, mem, dec_w,
                                               (__half2*)EW, (__half2*)MEM,
                                               (__half2*)DW, MT);
    }

    // 1) encoded = tanh(seq @ enc_w^T + enc_b) -> fp16 (seq converted inline)
    {
        dim3 grid(D_K / 128, NTOK / 128);
        gemm_enc<<<grid, 256, SM_G1>>>(seq, EW, enc_b, E);
    }
    // 2) fused logits + softmax -> att fp32 (d_out) + AT fp16
    logits_softmax<<<NTOK / 128, 256, SM_LS>>>(E, MEM, att, AT);

    // 3) memory = att @ mem -> memo fp32 (d_out) + M fp16   (K=64: 1 chunk)
    {
        dim3 grid(D_K / 128, NTOK / 128);
        mma_gemm<128, 2><<<grid, 256, SM128K>>>(AT, MT, nullptr, memo, M,
                                                D_K, MSLOTS);
    }
    // 4) recon = M @ dec_w^T + dec_b -> fp32 (d_out)        (K=256: 4 chunks)
    {
        dim3 grid(D_IN / 128, NTOK / 128);
        mma_gemm<128, 3><<<grid, 256, SM128K>>>(M, DW, dec_b, recon, nullptr,
                                                D_IN, D_K);
    }
}

// round 13
// speedup vs baseline: 1.5130x; 1.1355x over previous
#include <cuda_runtime.h>
#include <cuda_fp16.h>
#include <stdint.h>
#include <math.h>

#define NTOK   (16 * 4096)   // 65536 tokens
#define D_IN   512
#define D_K    256
#define MSLOTS 64

// ---------------------------------------------------------------------------
// Scratch (fp16 representations)
// ---------------------------------------------------------------------------
__device__ __align__(256) __half g_E[(size_t)NTOK * D_K];     // encoded fp16
__device__ __align__(256) __half g_AT[(size_t)NTOK * MSLOTS]; // attention fp16
__device__ __align__(256) __half g_EW[D_K * D_IN];            // enc_w fp16
__device__ __align__(256) __half g_MEM[MSLOTS * D_K];         // mem fp16
__device__ __align__(256) __half g_MT[D_K * MSLOTS];          // mem^T fp16
__device__ __align__(256) __half g_W2T[D_IN * MSLOTS];        // (dec_w @ mem^T) fp16

// ---------------------------------------------------------------------------
// PTX helpers
// ---------------------------------------------------------------------------
__device__ __forceinline__ uint32_t smem_u32(const void* p) {
    uint32_t a;
    asm("{ .reg .u64 t; cvta.to.shared.u64 t, %1; cvt.u32.u64 %0, t; }"
        : "=r"(a) : "l"(p));
    return a;
}
__device__ __forceinline__ void cp16(uint32_t dst, const void* src) {
    asm volatile("cp.async.cg.shared.global [%0], [%1], 16;"
                 :: "r"(dst), "l"(src));
}
__device__ __forceinline__ void cp_commit() {
    asm volatile("cp.async.commit_group;");
}
__device__ __forceinline__ void cp_wait0() {
    asm volatile("cp.async.wait_group 0;" ::: "memory");
}
__device__ __forceinline__ void cp_wait1() {
    asm volatile("cp.async.wait_group 1;" ::: "memory");
}

#define LDSM4(r0, r1, r2, r3, addr)                                            \
    asm volatile("ldmatrix.sync.aligned.m8n8.x4.shared.b16 {%0,%1,%2,%3}, [%4];" \
                 : "=r"(r0), "=r"(r1), "=r"(r2), "=r"(r3) : "r"(addr))
#define LDSM2(r0, r1, addr)                                                    \
    asm volatile("ldmatrix.sync.aligned.m8n8.x2.shared.b16 {%0,%1}, [%2];"     \
                 : "=r"(r0), "=r"(r1) : "r"(addr))
#define MMA16816(c, a, b)                                                      \
    asm volatile(                                                              \
        "mma.sync.aligned.m16n8k16.row.col.f32.f16.f16.f32 "                   \
        "{%0,%1,%2,%3},{%4,%5,%6,%7},{%8,%9},{%0,%1,%2,%3};"                   \
        : "+f"((c)[0]), "+f"((c)[1]), "+f"((c)[2]), "+f"((c)[3])               \
        : "r"((a)[0]), "r"((a)[1]), "r"((a)[2]), "r"((a)[3]),                  \
          "r"((b)[0]), "r"((b)[1]))

// ---------------------------------------------------------------------------
// K1: encoded = tanh(seq @ enc_w^T + enc_b). seq fp32 converted in-kernel.
// (round-11/12 passing version, unchanged)
// ---------------------------------------------------------------------------
__global__ __launch_bounds__(256, 2)
void gemm_enc(const float* __restrict__ A,
              const __half* __restrict__ B,
              const float* __restrict__ bias,
              __half* __restrict__ E)
{
    constexpr int AF32_BYTES = 128 * 144;
    constexpr int B_BYTES    = 128 * 80;
    constexpr int OFF_AF = 0;
    constexpr int OFF_B  = 2 * AF32_BYTES;
    constexpr int OFF_AH = OFF_B + 2 * B_BYTES;

    extern __shared__ char smem[];
    const uint32_t sb = smem_u32(smem);
    const int tid = threadIdx.x, lane = tid & 31, wid = tid >> 5;
    const int wm = wid & 1, wn = wid >> 1;
    const int m0 = blockIdx.y * 128;
    const int n0 = blockIdx.x * 128;

    float c[4][4][4];
#pragma unroll
    for (int mi = 0; mi < 4; mi++)
#pragma unroll
        for (int ni = 0; ni < 4; ni++)
#pragma unroll
            for (int j = 0; j < 4; j++) c[mi][ni][j] = 0.f;

    auto load_chunk = [&](int ch) {
        const int kc = ch * 32;
        const uint32_t stA = sb + OFF_AF + (uint32_t)((ch & 1) * AF32_BYTES);
        const uint32_t stB = sb + OFF_B  + (uint32_t)((ch & 1) * B_BYTES);
#pragma unroll
        for (int i = 0; i < 4; i++) {
            int e = tid + i * 256;
            int r = e >> 3, g = e & 7;
            cp16(stA + (uint32_t)(r * 144 + g * 16),
                 A + (size_t)(m0 + r) * D_IN + kc + g * 4);
        }
#pragma unroll
        for (int i = 0; i < 2; i++) {
            int e = tid + i * 256;
            int r = e >> 2, g = e & 3;
            cp16(stB + (uint32_t)(r * 80 + g * 16),
                 B + (size_t)(n0 + r) * D_IN + kc + g * 8);
        }
        cp_commit();
    };

    load_chunk(0);

    const uint32_t aRow = (uint32_t)((wm * 64 + (lane & 15)) * 80 + (lane >> 4) * 16);
    const uint32_t bRow = (uint32_t)((wn * 32 + (lane & 7)) * 80 + ((lane >> 3) & 1) * 16);
    const int cr  = tid & 127;
    const int chf = tid >> 7;

    for (int ch = 0; ch < 16; ch++) {
        cp_wait0();
        __syncthreads();

        {
            const char* src = smem + OFF_AF + (ch & 1) * AF32_BYTES
                            + cr * 144 + chf * 64;
            float4 f0 = *(const float4*)(src);
            float4 f1 = *(const float4*)(src + 16);
            float4 f2 = *(const float4*)(src + 32);
            float4 f3 = *(const float4*)(src + 48);
            __half2 h[8];
            h[0] = __floats2half2_rn(f0.x, f0.y);
            h[1] = __floats2half2_rn(f0.z, f0.w);
            h[2] = __floats2half2_rn(f1.x, f1.y);
            h[3] = __floats2half2_rn(f1.z, f1.w);
            h[4] = __floats2half2_rn(f2.x, f2.y);
            h[5] = __floats2half2_rn(f2.z, f2.w);
            h[6] = __floats2half2_rn(f3.x, f3.y);
            h[7] = __floats2half2_rn(f3.z, f3.w);
            uint4* dst = (uint4*)(smem + OFF_AH + cr * 80 + chf * 32);
            uint4 u0, u1;
            u0.x = *(uint32_t*)&h[0]; u0.y = *(uint32_t*)&h[1];
            u0.z = *(uint32_t*)&h[2]; u0.w = *(uint32_t*)&h[3];
            u1.x = *(uint32_t*)&h[4]; u1.y = *(uint32_t*)&h[5];
            u1.z = *(uint32_t*)&h[6]; u1.w = *(uint32_t*)&h[7];
            dst[0] = u0; dst[1] = u1;
        }

        if (ch + 1 < 16) load_chunk(ch + 1);
        __syncthreads();

        const uint32_t stB = sb + OFF_B + (uint32_t)((ch & 1) * B_BYTES);
#pragma unroll
        for (int kk = 0; kk < 2; kk++) {
            uint32_t a[4][4], b[4][2];
#pragma unroll
            for (int mi = 0; mi < 4; mi++) {
                uint32_t ad = sb + OFF_AH + aRow + (uint32_t)(mi * 1280 + kk * 32);
                LDSM4(a[mi][0], a[mi][1], a[mi][2], a[mi][3], ad);
            }
#pragma unroll
            for (int ni = 0; ni < 4; ni++) {
                uint32_t bd = stB + bRow + (uint32_t)(ni * 640 + kk * 32);
                LDSM2(b[ni][0], b[ni][1], bd);
            }
#pragma unroll
            for (int mi = 0; mi < 4; mi++)
#pragma unroll
                for (int ni = 0; ni < 4; ni++)
                    MMA16816(c[mi][ni], a[mi], b[ni]);
        }
    }

    const int r_in = lane >> 2, cpair = (lane & 3) * 2;
#pragma unroll
    for (int mi = 0; mi < 4; mi++) {
        const int rg = m0 + wm * 64 + mi * 16 + r_in;
#pragma unroll
        for (int ni = 0; ni < 4; ni++) {
            const int cg = n0 + wn * 32 + ni * 8 + cpair;
            float b0 = bias[cg], b1 = bias[cg + 1];
            float v0 = tanhf(c[mi][ni][0] + b0);
            float v1 = tanhf(c[mi][ni][1] + b1);
            float v2 = tanhf(c[mi][ni][2] + b0);
            float v3 = tanhf(c[mi][ni][3] + b1);
            *(__half2*)(E + (size_t)rg * D_K + cg)       = __floats2half2_rn(v0, v1);
            *(__half2*)(E + (size_t)(rg + 8) * D_K + cg) = __floats2half2_rn(v2, v3);
        }
    }
}

// ---------------------------------------------------------------------------
// Generic fp16 GEMM, BK=64, 3-stage pipeline (round-12 proven).
// EPI: 3 = +bias, write fp32 (Cf);  4 = identity, write fp32 (Cf) only.
// ---------------------------------------------------------------------------
template <int NT, int EPI>
__global__ __launch_bounds__(256, 2)
void mma_gemm(const __half* __restrict__ A,
              const __half* __restrict__ B,
              const float* __restrict__ bias,
              float* __restrict__ Cf,
              int Ntotal, int K)
{
    constexpr int NW  = NT / 32;
    constexpr int NWC = NT / 4;
    constexpr int A_BYTES = 128 * 144;
    constexpr int B_BYTES = NT * 144;
    constexpr int OFF_A = 0, OFF_B = A_BYTES;
    constexpr int STAGE = A_BYTES + B_BYTES;

    extern __shared__ char smem[];
    const uint32_t sb = smem_u32(smem);

    const int tid  = threadIdx.x;
    const int lane = tid & 31;
    const int wid  = tid >> 5;
    const int wm   = wid & 1;
    const int wn   = wid >> 1;
    const int m0   = blockIdx.y * 128;
    const int n0   = blockIdx.x * NT;

    float c[4][NW][4];
#pragma unroll
    for (int mi = 0; mi < 4; mi++)
#pragma unroll
        for (int ni = 0; ni < NW; ni++)
#pragma unroll
            for (int j = 0; j < 4; j++) c[mi][ni][j] = 0.f;

    const int nch = K >> 6;

    auto load_chunk = [&](int ch) {
        if (ch < nch) {
            const uint32_t st = sb + (uint32_t)((ch % 3) * STAGE);
            const int kc = ch * 64;
#pragma unroll
            for (int i = 0; i < 4; i++) {
                int e = tid + i * 256;
                int r = e >> 3, g = e & 7;
                cp16(st + OFF_A + (uint32_t)(r * 144 + g * 16),
                     A + (size_t)(m0 + r) * K + kc + g * 8);
            }
#pragma unroll
            for (int i = 0; i < NT / 32; i++) {
                int e = tid + i * 256;
                int r = e >> 3, g = e & 7;
                cp16(st + OFF_B + (uint32_t)(r * 144 + g * 16),
                     B + (size_t)(n0 + r) * K + kc + g * 8);
            }
        }
        cp_commit();
    };

    load_chunk(0);
    load_chunk(1);

    const uint32_t aRow = (uint32_t)((wm * 64 + (lane & 15)) * 144 + (lane >> 4) * 16);
    const uint32_t bRow = (uint32_t)((wn * NWC + (lane & 7)) * 144 + ((lane >> 3) & 1) * 16);

    for (int ch = 0; ch < nch; ch++) {
        cp_wait1();
        __syncthreads();
        load_chunk(ch + 2);

        const uint32_t st = sb + (uint32_t)((ch % 3) * STAGE);
#pragma unroll
        for (int kk = 0; kk < 4; kk++) {
            uint32_t a[4][4], b[NW][2];
#pragma unroll
            for (int mi = 0; mi < 4; mi++) {
                uint32_t ad = st + OFF_A + aRow + (uint32_t)(mi * 2304 + kk * 32);
                LDSM4(a[mi][0], a[mi][1], a[mi][2], a[mi][3], ad);
            }
#pragma unroll
            for (int ni = 0; ni < NW; ni++) {
                uint32_t bd = st + OFF_B + bRow + (uint32_t)(ni * 1152 + kk * 32);
                LDSM2(b[ni][0], b[ni][1], bd);
            }
#pragma unroll
            for (int mi = 0; mi < 4; mi++)
#pragma unroll
                for (int ni = 0; ni < NW; ni++)
                    MMA16816(c[mi][ni], a[mi], b[ni]);
        }
    }

    const int r_in  = lane >> 2;
    const int cpair = (lane & 3) * 2;
#pragma unroll
    for (int mi = 0; mi < 4; mi++) {
        const int rg = m0 + wm * 64 + mi * 16 + r_in;
#pragma unroll
        for (int ni = 0; ni < NW; ni++) {
            const int cg = n0 + wn * NWC + ni * 8 + cpair;
            float v0 = c[mi][ni][0], v1 = c[mi][ni][1];
            float v2 = c[mi][ni][2], v3 = c[mi][ni][3];
            if (EPI == 3) {
                float b0 = bias[cg], b1 = bias[cg + 1];
                v0 += b0; v1 += b1; v2 += b0; v3 += b1;
            }
            *(float2*)(Cf + (size_t)rg * Ntotal + cg)       = make_float2(v0, v1);
            *(float2*)(Cf + (size_t)(rg + 8) * Ntotal + cg) = make_float2(v2, v3);
        }
    }
}

// ---------------------------------------------------------------------------
// Fused logits + softmax (unchanged passing version)
// ---------------------------------------------------------------------------
__global__ __launch_bounds__(256)
void logits_softmax(const __half* __restrict__ E,
                    const __half* __restrict__ MEMp,
                    float* __restrict__ att,
                    __half* __restrict__ AT)
{
    constexpr int A_BYTES = 10240, B_BYTES = 64 * 80;
    constexpr int OFF_A = 0, OFF_B = A_BYTES;
    constexpr int STAGE = A_BYTES + B_BYTES;
    constexpr int OFF_LG = 2 * STAGE;

    extern __shared__ char smem[];
    const uint32_t sb = smem_u32(smem);
    const int tid = threadIdx.x, lane = tid & 31, wid = tid >> 5;
    const int wm = wid & 1, wn = wid >> 1;
    const int m0 = blockIdx.x * 128;

    float c[4][2][4];
#pragma unroll
    for (int mi = 0; mi < 4; mi++)
#pragma unroll
        for (int ni = 0; ni < 2; ni++)
#pragma unroll
            for (int j = 0; j < 4; j++) c[mi][ni][j] = 0.f;

    auto load_chunk = [&](int ch) {
        const uint32_t st = sb + (uint32_t)((ch & 1) * STAGE);
        const int kc = ch * 32;
#pragma unroll
        for (int i = 0; i < 2; i++) {
            int e = tid + i * 256;
            int r = e >> 2, g = e & 3;
            cp16(st + OFF_A + (uint32_t)(r * 80 + g * 16),
                 E + (size_t)(m0 + r) * D_K + kc + g * 8);
        }
        {
            int r = tid >> 2, g = tid & 3;
            if (r < 64)
                cp16(st + OFF_B + (uint32_t)(r * 80 + g * 16),
                     MEMp + (size_t)r * D_K + kc + g * 8);
        }
        cp_commit();
    };

    load_chunk(0);

    const uint32_t aRow = (uint32_t)((wm * 64 + (lane & 15)) * 80 + (lane >> 4) * 16);
    const uint32_t bRow = (uint32_t)((wn * 16 + (lane & 7)) * 80 + ((lane >> 3) & 1) * 16);

    for (int ch = 0; ch < 8; ch++) {
        cp_wait0();
        __syncthreads();
        if (ch + 1 < 8) load_chunk(ch + 1);

        const uint32_t st = sb + (uint32_t)((ch & 1) * STAGE);
#pragma unroll
        for (int kk = 0; kk < 2; kk++) {
            uint32_t a[4][4], b[2][2];
#pragma unroll
            for (int mi = 0; mi < 4; mi++) {
                uint32_t ad = st + OFF_A + aRow + (uint32_t)(mi * 1280 + kk * 32);
                LDSM4(a[mi][0], a[mi][1], a[mi][2], a[mi][3], ad);
            }
#pragma unroll
            for (int ni = 0; ni < 2; ni++) {
                uint32_t bd = st + OFF_B + bRow + (uint32_t)(ni * 640 + kk * 32);
                LDSM2(b[ni][0], b[ni][1], bd);
            }
#pragma unroll
            for (int mi = 0; mi < 4; mi++)
#pragma unroll
                for (int ni = 0; ni < 2; ni++)
                    MMA16816(c[mi][ni], a[mi], b[ni]);
        }
        __syncthreads();
    }

    float* LGf = (float*)(smem + OFF_LG);
    const int r_in = lane >> 2, cpair = (lane & 3) * 2;
#pragma unroll
    for (int mi = 0; mi < 4; mi++) {
        const int rl = wm * 64 + mi * 16 + r_in;
#pragma unroll
        for (int ni = 0; ni < 2; ni++) {
            const int cl = wn * 16 + ni * 8 + cpair;
            LGf[rl * 68 + cl]           = c[mi][ni][0] * 0.0625f;
            LGf[rl * 68 + cl + 1]       = c[mi][ni][1] * 0.0625f;
            LGf[(rl + 8) * 68 + cl]     = c[mi][ni][2] * 0.0625f;
            LGf[(rl + 8) * 68 + cl + 1] = c[mi][ni][3] * 0.0625f;
        }
    }
    __syncthreads();

    {
        const int row = tid >> 1, half = tid & 1;
        float* lr = LGf + row * 68 + half * 32;
        float mx = lr[0];
#pragma unroll 8
        for (int j = 1; j < 32; j++) mx = fmaxf(mx, lr[j]);
        mx = fmaxf(mx, __shfl_xor_sync(0xffffffffu, mx, 1));
        float sum = 0.f;
#pragma unroll 8
        for (int j = 0; j < 32; j++) {
            float p = expf(lr[j] - mx);
            lr[j] = p;
            sum += p;
        }
        sum += __shfl_xor_sync(0xffffffffu, sum, 1);
        float inv = 1.f / sum;
#pragma unroll 8
        for (int j = 0; j < 32; j++) lr[j] *= inv;
    }
    __syncthreads();

#pragma unroll
    for (int i = 0; i < 32; i++) {
        int idx = tid + i * 256;
        int r = idx >> 6, cc = idx & 63;
        float v = LGf[r * 68 + cc];
        att[(size_t)(m0 + r) * 64 + cc] = v;
        AT[(size_t)(m0 + r) * 64 + cc]  = __float2half_rn(v);
    }
}

// ---------------------------------------------------------------------------
// W2T[d, m] = sum_k dec_w[d,k] * mem[m,k]  (fp32 accumulate from fp32 inputs,
// rounded to fp16 once). 32768 outputs, one thread each.
// ---------------------------------------------------------------------------
__global__ void compute_w2t(const float* __restrict__ dec_w,
                            const float* __restrict__ mem,
                            __half* __restrict__ W2T)
{
    int idx = blockIdx.x * blockDim.x + threadIdx.x;
    if (idx >= D_IN * MSLOTS) return;
    int d = idx >> 6, m = idx & 63;
    const float4* dw = (const float4*)(dec_w + (size_t)d * D_K);
    const float4* mm = (const float4*)(mem + (size_t)m * D_K);
    float s = 0.f;
#pragma unroll 8
    for (int k = 0; k < D_K / 4; k++) {
        float4 a = dw[k], b = mm[k];
        s += a.x * b.x + a.y * b.y + a.z * b.z + a.w * b.w;
    }
    W2T[idx] = __float2half_rn(s);
}

// ---------------------------------------------------------------------------
// Weight conversions (EW, MEM, MT only)
// ---------------------------------------------------------------------------
__global__ void cvt_weights(const float* __restrict__ enc_w,
                            const float* __restrict__ mem,
                            __half2* __restrict__ EW,
                            __half2* __restrict__ MEM2,
                            __half* __restrict__ MT)
{
    int i = blockIdx.x * blockDim.x + threadIdx.x;
    if (i < 32768) {
        float4 v = ((const float4*)enc_w)[i];
        EW[2*i]   = __floats2half2_rn(v.x, v.y);
        EW[2*i+1] = __floats2half2_rn(v.z, v.w);
    } else if (i < 32768 + 4096) {
        int j = i - 32768;
        float4 v = ((const float4*)mem)[j];
        MEM2[2*j]   = __floats2half2_rn(v.x, v.y);
        MEM2[2*j+1] = __floats2half2_rn(v.z, v.w);
    } else if (i < 32768 + 4096 + 16384) {
        int j = i - 32768 - 4096;
        int r = j >> 8, cc = j & 255;
        MT[(size_t)cc * MSLOTS + r] = __float2half_rn(mem[j]);
    }
}

// ---------------------------------------------------------------------------
// launch
// ---------------------------------------------------------------------------
extern "C" void kernel_launch(void* const* d_in, const int* in_sizes, int n_in,
                              void* d_out, int out_size)
{
    const float* seq   = (const float*)d_in[0];
    const float* enc_w = (const float*)d_in[1];
    const float* enc_b = (const float*)d_in[2];
    const float* mem   = (const float*)d_in[3];
    const float* dec_w = (const float*)d_in[4];
    const float* dec_b = (const float*)d_in[5];

    float* out   = (float*)d_out;
    float* recon = out;
    float* att   = out + (size_t)NTOK * D_IN;
    float* memo  = att + (size_t)NTOK * MSLOTS;

    __half *E, *AT, *EW, *MEM, *MT, *W2T;
    cudaGetSymbolAddress((void**)&E, g_E);
    cudaGetSymbolAddress((void**)&AT, g_AT);
    cudaGetSymbolAddress((void**)&EW, g_EW);
    cudaGetSymbolAddress((void**)&MEM, g_MEM);
    cudaGetSymbolAddress((void**)&MT, g_MT);
    cudaGetSymbolAddress((void**)&W2T, g_W2T);

    const int SM_G1  = 2 * 18432 + 2 * 10240 + 10240;   // 67584
    const int SM128K = 3 * (18432 + 128 * 144);         // 110592
    const int SM_LS  = 2 * (10240 + 64 * 80) + 34816;   // 65536
    cudaFuncSetAttribute(gemm_enc,         cudaFuncAttributeMaxDynamicSharedMemorySize, SM_G1);
    cudaFuncSetAttribute(logits_softmax,   cudaFuncAttributeMaxDynamicSharedMemorySize, SM_LS);
    cudaFuncSetAttribute(mma_gemm<128, 4>, cudaFuncAttributeMaxDynamicSharedMemorySize, SM128K);
    cudaFuncSetAttribute(mma_gemm<128, 3>, cudaFuncAttributeMaxDynamicSharedMemorySize, SM128K);

    // prep: weight conversions + W2T (2 small launches)
    {
        const int nW = 32768 + 4096 + 16384;
        cvt_weights<<<(nW + 255) / 256, 256>>>(enc_w, mem,
                                               (__half2*)EW, (__half2*)MEM, MT);
        compute_w2t<<<(D_IN * MSLOTS + 255) / 256, 256>>>(dec_w, mem, W2T);
    }

    // 1) encoded = tanh(seq @ enc_w^T + enc_b) -> fp16 (seq converted inline)
    {
        dim3 grid(D_K / 128, NTOK / 128);
        gemm_enc<<<grid, 256, SM_G1>>>(seq, EW, enc_b, E);
    }
    // 2) fused logits + softmax -> att fp32 (d_out) + AT fp16
    logits_softmax<<<NTOK / 128, 256, SM_LS>>>(E, MEM, att, AT);

    // 3) memo = att @ mem (K=64) -> fp32 (d_out)
    {
        dim3 grid(D_K / 128, NTOK / 128);
        mma_gemm<128, 4><<<grid, 256, SM128K>>>(AT, MT, nullptr, memo,
                                                D_K, MSLOTS);
    }
    // 4) recon = att @ W2T^T + dec_b (K=64) -> fp32 (d_out)
    {
        dim3 grid(D_IN / 128, NTOK / 128);
        mma_gemm<128, 3><<<grid, 256, SM128K>>>(AT, W2T, dec_b, recon,
                                                D_IN, MSLOTS);
    }
}

// round 14
// speedup vs baseline: 1.5329x; 1.0131x over previous
#include <cuda_runtime.h>
#include <cuda_fp16.h>
#include <stdint.h>
#include <math.h>

#define NTOK   (16 * 4096)   // 65536 tokens
#define D_IN   512
#define D_K    256
#define MSLOTS 64

// ---------------------------------------------------------------------------
// Scratch
// ---------------------------------------------------------------------------
__device__ __align__(256) __half g_E[(size_t)NTOK * D_K];     // encoded fp16
__device__ __align__(256) __half g_EW[D_K * D_IN];            // enc_w fp16
__device__ __align__(256) __half g_MEM[MSLOTS * D_K];         // mem fp16
__device__ __align__(256) __half g_MT[D_K * MSLOTS];          // mem^T fp16
__device__ __align__(256) __half g_W2T[D_IN * MSLOTS];        // (dec_w @ mem^T) fp16

// ---------------------------------------------------------------------------
// PTX helpers
// ---------------------------------------------------------------------------
__device__ __forceinline__ uint32_t smem_u32(const void* p) {
    uint32_t a;
    asm("{ .reg .u64 t; cvta.to.shared.u64 t, %1; cvt.u32.u64 %0, t; }"
        : "=r"(a) : "l"(p));
    return a;
}
__device__ __forceinline__ void cp16(uint32_t dst, const void* src) {
    asm volatile("cp.async.cg.shared.global [%0], [%1], 16;"
                 :: "r"(dst), "l"(src));
}
__device__ __forceinline__ void cp_commit() {
    asm volatile("cp.async.commit_group;");
}
__device__ __forceinline__ void cp_wait0() {
    asm volatile("cp.async.wait_group 0;" ::: "memory");
}
__device__ __forceinline__ void cp_wait1() {
    asm volatile("cp.async.wait_group 1;" ::: "memory");
}

#define LDSM4(r0, r1, r2, r3, addr)                                            \
    asm volatile("ldmatrix.sync.aligned.m8n8.x4.shared.b16 {%0,%1,%2,%3}, [%4];" \
                 : "=r"(r0), "=r"(r1), "=r"(r2), "=r"(r3) : "r"(addr))
#define LDSM2(r0, r1, addr)                                                    \
    asm volatile("ldmatrix.sync.aligned.m8n8.x2.shared.b16 {%0,%1}, [%2];"     \
                 : "=r"(r0), "=r"(r1) : "r"(addr))
#define MMA16816(c, a, b)                                                      \
    asm volatile(                                                              \
        "mma.sync.aligned.m16n8k16.row.col.f32.f16.f16.f32 "                   \
        "{%0,%1,%2,%3},{%4,%5,%6,%7},{%8,%9},{%0,%1,%2,%3};"                   \
        : "+f"((c)[0]), "+f"((c)[1]), "+f"((c)[2]), "+f"((c)[3])               \
        : "r"((a)[0]), "r"((a)[1]), "r"((a)[2]), "r"((a)[3]),                  \
          "r"((b)[0]), "r"((b)[1]))

// ---------------------------------------------------------------------------
// K1: encoded = tanh(seq @ enc_w^T + enc_b). seq fp32 converted in-kernel.
// (round-11/12/13 passing version, unchanged)
// ---------------------------------------------------------------------------
__global__ __launch_bounds__(256, 2)
void gemm_enc(const float* __restrict__ A,
              const __half* __restrict__ B,
              const float* __restrict__ bias,
              __half* __restrict__ E)
{
    constexpr int AF32_BYTES = 128 * 144;
    constexpr int B_BYTES    = 128 * 80;
    constexpr int OFF_AF = 0;
    constexpr int OFF_B  = 2 * AF32_BYTES;
    constexpr int OFF_AH = OFF_B + 2 * B_BYTES;

    extern __shared__ char smem[];
    const uint32_t sb = smem_u32(smem);
    const int tid = threadIdx.x, lane = tid & 31, wid = tid >> 5;
    const int wm = wid & 1, wn = wid >> 1;
    const int m0 = blockIdx.y * 128;
    const int n0 = blockIdx.x * 128;

    float c[4][4][4];
#pragma unroll
    for (int mi = 0; mi < 4; mi++)
#pragma unroll
        for (int ni = 0; ni < 4; ni++)
#pragma unroll
            for (int j = 0; j < 4; j++) c[mi][ni][j] = 0.f;

    auto load_chunk = [&](int ch) {
        const int kc = ch * 32;
        const uint32_t stA = sb + OFF_AF + (uint32_t)((ch & 1) * AF32_BYTES);
        const uint32_t stB = sb + OFF_B  + (uint32_t)((ch & 1) * B_BYTES);
#pragma unroll
        for (int i = 0; i < 4; i++) {
            int e = tid + i * 256;
            int r = e >> 3, g = e & 7;
            cp16(stA + (uint32_t)(r * 144 + g * 16),
                 A + (size_t)(m0 + r) * D_IN + kc + g * 4);
        }
#pragma unroll
        for (int i = 0; i < 2; i++) {
            int e = tid + i * 256;
            int r = e >> 2, g = e & 3;
            cp16(stB + (uint32_t)(r * 80 + g * 16),
                 B + (size_t)(n0 + r) * D_IN + kc + g * 8);
        }
        cp_commit();
    };

    load_chunk(0);

    const uint32_t aRow = (uint32_t)((wm * 64 + (lane & 15)) * 80 + (lane >> 4) * 16);
    const uint32_t bRow = (uint32_t)((wn * 32 + (lane & 7)) * 80 + ((lane >> 3) & 1) * 16);
    const int cr  = tid & 127;
    const int chf = tid >> 7;

    for (int ch = 0; ch < 16; ch++) {
        cp_wait0();
        __syncthreads();

        {
            const char* src = smem + OFF_AF + (ch & 1) * AF32_BYTES
                            + cr * 144 + chf * 64;
            float4 f0 = *(const float4*)(src);
            float4 f1 = *(const float4*)(src + 16);
            float4 f2 = *(const float4*)(src + 32);
            float4 f3 = *(const float4*)(src + 48);
            __half2 h[8];
            h[0] = __floats2half2_rn(f0.x, f0.y);
            h[1] = __floats2half2_rn(f0.z, f0.w);
            h[2] = __floats2half2_rn(f1.x, f1.y);
            h[3] = __floats2half2_rn(f1.z, f1.w);
            h[4] = __floats2half2_rn(f2.x, f2.y);
            h[5] = __floats2half2_rn(f2.z, f2.w);
            h[6] = __floats2half2_rn(f3.x, f3.y);
            h[7] = __floats2half2_rn(f3.z, f3.w);
            uint4* dst = (uint4*)(smem + OFF_AH + cr * 80 + chf * 32);
            uint4 u0, u1;
            u0.x = *(uint32_t*)&h[0]; u0.y = *(uint32_t*)&h[1];
            u0.z = *(uint32_t*)&h[2]; u0.w = *(uint32_t*)&h[3];
            u1.x = *(uint32_t*)&h[4]; u1.y = *(uint32_t*)&h[5];
            u1.z = *(uint32_t*)&h[6]; u1.w = *(uint32_t*)&h[7];
            dst[0] = u0; dst[1] = u1;
        }

        if (ch + 1 < 16) load_chunk(ch + 1);
        __syncthreads();

        const uint32_t stB = sb + OFF_B + (uint32_t)((ch & 1) * B_BYTES);
#pragma unroll
        for (int kk = 0; kk < 2; kk++) {
            uint32_t a[4][4], b[4][2];
#pragma unroll
            for (int mi = 0; mi < 4; mi++) {
                uint32_t ad = sb + OFF_AH + aRow + (uint32_t)(mi * 1280 + kk * 32);
                LDSM4(a[mi][0], a[mi][1], a[mi][2], a[mi][3], ad);
            }
#pragma unroll
            for (int ni = 0; ni < 4; ni++) {
                uint32_t bd = stB + bRow + (uint32_t)(ni * 640 + kk * 32);
                LDSM2(b[ni][0], b[ni][1], bd);
            }
#pragma unroll
            for (int mi = 0; mi < 4; mi++)
#pragma unroll
                for (int ni = 0; ni < 4; ni++)
                    MMA16816(c[mi][ni], a[mi], b[ni]);
        }
    }

    const int r_in = lane >> 2, cpair = (lane & 3) * 2;
#pragma unroll
    for (int mi = 0; mi < 4; mi++) {
        const int rg = m0 + wm * 64 + mi * 16 + r_in;
#pragma unroll
        for (int ni = 0; ni < 4; ni++) {
            const int cg = n0 + wn * 32 + ni * 8 + cpair;
            float b0 = bias[cg], b1 = bias[cg + 1];
            float v0 = tanhf(c[mi][ni][0] + b0);
            float v1 = tanhf(c[mi][ni][1] + b1);
            float v2 = tanhf(c[mi][ni][2] + b0);
            float v3 = tanhf(c[mi][ni][3] + b1);
            *(__half2*)(E + (size_t)rg * D_K + cg)       = __floats2half2_rn(v0, v1);
            *(__half2*)(E + (size_t)(rg + 8) * D_K + cg) = __floats2half2_rn(v2, v3);
        }
    }
}

// ---------------------------------------------------------------------------
// K2: fused logits + softmax + memo + recon. Per CTA (128 tokens):
//   phase 1: logits = E @ MEM^T / 16 -> LG smem; softmax;
//            att fp32 -> d_out; att fp16 -> smem tile (pitch 144)
//   phase 2: 6 N-chunks of 128: j<2 -> memo = att@MT; j>=2 -> recon = att@W2T + dec_b
// smem layout (total 67584):
//   [0, 30720)      phase1 pipe (2 x (E 10240 + MEM 5120)); phase2: att16 [0,18432)
//   [30720, 65536)  LG (128 x 68 fp32); phase2: B double buffer [30720, 67584)
//   (B overlays LG only after all LG reads complete; cp.async issued post-sync)
// ---------------------------------------------------------------------------
__global__ __launch_bounds__(256)
void attn_fused(const __half* __restrict__ E,
                const __half* __restrict__ MEMp,
                const __half* __restrict__ MTp,
                const __half* __restrict__ W2Tp,
                const float* __restrict__ dec_b,
                float* __restrict__ att,
                float* __restrict__ memo,
                float* __restrict__ recon)
{
    constexpr int A_BYTES = 10240, B1_BYTES = 64 * 80;
    constexpr int OFF_A = 0, OFF_B1 = A_BYTES;
    constexpr int STAGE1 = A_BYTES + B1_BYTES;   // 15360
    constexpr int OFF_LG  = 2 * STAGE1;          // 30720
    constexpr int OFF_AT16 = 0;                  // phase2, over pipe region
    constexpr int OFF_B2  = 30720;               // phase2, 2 x 18432 over LG

    extern __shared__ char smem[];
    const uint32_t sb = smem_u32(smem);
    const int tid = threadIdx.x, lane = tid & 31, wid = tid >> 5;
    const int wm = wid & 1, wn = wid >> 1;
    const int m0 = blockIdx.x * 128;
    const int r_in = lane >> 2, cpair = (lane & 3) * 2;

    // ================= phase 1: logits =================
    float c1[4][2][4];
#pragma unroll
    for (int mi = 0; mi < 4; mi++)
#pragma unroll
        for (int ni = 0; ni < 2; ni++)
#pragma unroll
            for (int j = 0; j < 4; j++) c1[mi][ni][j] = 0.f;

    auto load_chunk1 = [&](int ch) {
        const uint32_t st = sb + (uint32_t)((ch & 1) * STAGE1);
        const int kc = ch * 32;
#pragma unroll
        for (int i = 0; i < 2; i++) {
            int e = tid + i * 256;
            int r = e >> 2, g = e & 3;
            cp16(st + OFF_A + (uint32_t)(r * 80 + g * 16),
                 E + (size_t)(m0 + r) * D_K + kc + g * 8);
        }
        {
            int r = tid >> 2, g = tid & 3;
            if (r < 64)
                cp16(st + OFF_B1 + (uint32_t)(r * 80 + g * 16),
                     MEMp + (size_t)r * D_K + kc + g * 8);
        }
        cp_commit();
    };

    load_chunk1(0);

    const uint32_t aRow1 = (uint32_t)((wm * 64 + (lane & 15)) * 80 + (lane >> 4) * 16);
    const uint32_t bRow1 = (uint32_t)((wn * 16 + (lane & 7)) * 80 + ((lane >> 3) & 1) * 16);

    for (int ch = 0; ch < 8; ch++) {
        cp_wait0();
        __syncthreads();
        if (ch + 1 < 8) load_chunk1(ch + 1);

        const uint32_t st = sb + (uint32_t)((ch & 1) * STAGE1);
#pragma unroll
        for (int kk = 0; kk < 2; kk++) {
            uint32_t a[4][4], b[2][2];
#pragma unroll
            for (int mi = 0; mi < 4; mi++) {
                uint32_t ad = st + OFF_A + aRow1 + (uint32_t)(mi * 1280 + kk * 32);
                LDSM4(a[mi][0], a[mi][1], a[mi][2], a[mi][3], ad);
            }
#pragma unroll
            for (int ni = 0; ni < 2; ni++) {
                uint32_t bd = st + OFF_B1 + bRow1 + (uint32_t)(ni * 640 + kk * 32);
                LDSM2(b[ni][0], b[ni][1], bd);
            }
#pragma unroll
            for (int mi = 0; mi < 4; mi++)
#pragma unroll
                for (int ni = 0; ni < 2; ni++)
                    MMA16816(c1[mi][ni], a[mi], b[ni]);
        }
        __syncthreads();
    }

    // ---- scaled logits -> LG
    float* LGf = (float*)(smem + OFF_LG);
#pragma unroll
    for (int mi = 0; mi < 4; mi++) {
        const int rl = wm * 64 + mi * 16 + r_in;
#pragma unroll
        for (int ni = 0; ni < 2; ni++) {
            const int cl = wn * 16 + ni * 8 + cpair;
            LGf[rl * 68 + cl]           = c1[mi][ni][0] * 0.0625f;
            LGf[rl * 68 + cl + 1]       = c1[mi][ni][1] * 0.0625f;
            LGf[(rl + 8) * 68 + cl]     = c1[mi][ni][2] * 0.0625f;
            LGf[(rl + 8) * 68 + cl + 1] = c1[mi][ni][3] * 0.0625f;
        }
    }
    __syncthreads();

    // ---- softmax: 2 threads per row
    {
        const int row = tid >> 1, half = tid & 1;
        float* lr = LGf + row * 68 + half * 32;
        float mx = lr[0];
#pragma unroll 8
        for (int j = 1; j < 32; j++) mx = fmaxf(mx, lr[j]);
        mx = fmaxf(mx, __shfl_xor_sync(0xffffffffu, mx, 1));
        float sum = 0.f;
#pragma unroll 8
        for (int j = 0; j < 32; j++) {
            float p = expf(lr[j] - mx);
            lr[j] = p;
            sum += p;
        }
        sum += __shfl_xor_sync(0xffffffffu, sum, 1);
        float inv = 1.f / sum;
#pragma unroll 8
        for (int j = 0; j < 32; j++) lr[j] *= inv;
    }
    __syncthreads();

    // ---- att fp32 -> gmem; att fp16 -> smem tile (pitch 144)
#pragma unroll
    for (int i = 0; i < 32; i++) {
        int idx = tid + i * 256;
        int r = idx >> 6, cc = idx & 63;
        float v = LGf[r * 68 + cc];
        att[(size_t)(m0 + r) * 64 + cc] = v;
        *(__half*)(smem + OFF_AT16 + r * 144 + cc * 2) = __float2half_rn(v);
    }
    __syncthreads();   // LG reads done; att16 visible; B loads may now overlay LG

    // ================= phase 2: memo + recon =================
    auto load_B2 = [&](int j) {
        if (j < 6) {
            const uint32_t st = sb + OFF_B2 + (uint32_t)((j & 1) * 18432);
            const __half* src = (j < 2) ? (MTp + (size_t)(j * 128) * MSLOTS)
                                        : (W2Tp + (size_t)((j - 2) * 128) * MSLOTS);
#pragma unroll
            for (int i = 0; i < 4; i++) {
                int e = tid + i * 256;
                int r = e >> 3, g = e & 7;
                cp16(st + (uint32_t)(r * 144 + g * 16),
                     src + (size_t)r * MSLOTS + g * 8);
            }
            cp_commit();
        }
    };

    load_B2(0);

    const uint32_t aRow2 = (uint32_t)((wm * 64 + (lane & 15)) * 144 + (lane >> 4) * 16);
    const uint32_t bRow2 = (uint32_t)((wn * 32 + (lane & 7)) * 144 + ((lane >> 3) & 1) * 16);

    for (int j = 0; j < 6; j++) {
        cp_wait0();
        __syncthreads();
        load_B2(j + 1);

        float c2[4][4][4];
#pragma unroll
        for (int mi = 0; mi < 4; mi++)
#pragma unroll
            for (int ni = 0; ni < 4; ni++)
#pragma unroll
                for (int q = 0; q < 4; q++) c2[mi][ni][q] = 0.f;

        const uint32_t stB = sb + OFF_B2 + (uint32_t)((j & 1) * 18432);
#pragma unroll
        for (int kk = 0; kk < 4; kk++) {
            uint32_t a[4][4], b[4][2];
#pragma unroll
            for (int mi = 0; mi < 4; mi++) {
                uint32_t ad = sb + OFF_AT16 + aRow2 + (uint32_t)(mi * 2304 + kk * 32);
                LDSM4(a[mi][0], a[mi][1], a[mi][2], a[mi][3], ad);
            }
#pragma unroll
            for (int ni = 0; ni < 4; ni++) {
                uint32_t bd = stB + bRow2 + (uint32_t)(ni * 1152 + kk * 32);
                LDSM2(b[ni][0], b[ni][1], bd);
            }
#pragma unroll
            for (int mi = 0; mi < 4; mi++)
#pragma unroll
                for (int ni = 0; ni < 4; ni++)
                    MMA16816(c2[mi][ni], a[mi], b[ni]);
        }

        // epilogue for this chunk
        const bool is_memo = (j < 2);
        float* Cf = is_memo ? memo : recon;
        const int Ntot = is_memo ? D_K : D_IN;
        const int n0 = (is_memo ? j : (j - 2)) * 128;
#pragma unroll
        for (int mi = 0; mi < 4; mi++) {
            const int rg = m0 + wm * 64 + mi * 16 + r_in;
#pragma unroll
            for (int ni = 0; ni < 4; ni++) {
                const int cg = n0 + wn * 32 + ni * 8 + cpair;
                float v0 = c2[mi][ni][0], v1 = c2[mi][ni][1];
                float v2 = c2[mi][ni][2], v3 = c2[mi][ni][3];
                if (!is_memo) {
                    float b0 = dec_b[cg], b1 = dec_b[cg + 1];
                    v0 += b0; v1 += b1; v2 += b0; v3 += b1;
                }
                *(float2*)(Cf + (size_t)rg * Ntot + cg)       = make_float2(v0, v1);
                *(float2*)(Cf + (size_t)(rg + 8) * Ntot + cg) = make_float2(v2, v3);
            }
        }
    }
}

// ---------------------------------------------------------------------------
// One merged prep kernel: weight conversions + W2T = dec_w @ mem^T
// ---------------------------------------------------------------------------
__global__ void prep_weights(const float* __restrict__ enc_w,
                             const float* __restrict__ mem,
                             const float* __restrict__ dec_w,
                             __half2* __restrict__ EW,
                             __half2* __restrict__ MEM2,
                             __half* __restrict__ MT,
                             __half* __restrict__ W2T)
{
    int i = blockIdx.x * blockDim.x + threadIdx.x;
    if (i < 32768) {
        float4 v = ((const float4*)enc_w)[i];
        EW[2*i]   = __floats2half2_rn(v.x, v.y);
        EW[2*i+1] = __floats2half2_rn(v.z, v.w);
    } else if (i < 32768 + 4096) {
        int j = i - 32768;
        float4 v = ((const float4*)mem)[j];
        MEM2[2*j]   = __floats2half2_rn(v.x, v.y);
        MEM2[2*j+1] = __floats2half2_rn(v.z, v.w);
    } else if (i < 32768 + 4096 + 16384) {
        int j = i - 32768 - 4096;
        int r = j >> 8, cc = j & 255;
        MT[(size_t)cc * MSLOTS + r] = __float2half_rn(mem[j]);
    } else if (i < 32768 + 4096 + 16384 + 32768) {
        int idx = i - 32768 - 4096 - 16384;    // over [512][64]
        int d = idx >> 6, m = idx & 63;
        const float4* dw = (const float4*)(dec_w + (size_t)d * D_K);
        const float4* mm = (const float4*)(mem + (size_t)m * D_K);
        float s = 0.f;
#pragma unroll 8
        for (int k = 0; k < D_K / 4; k++) {
            float4 a = dw[k], b = mm[k];
            s += a.x * b.x + a.y * b.y + a.z * b.z + a.w * b.w;
        }
        W2T[idx] = __float2half_rn(s);
    }
}

// ---------------------------------------------------------------------------
// launch
// ---------------------------------------------------------------------------
extern "C" void kernel_launch(void* const* d_in, const int* in_sizes, int n_in,
                              void* d_out, int out_size)
{
    const float* seq   = (const float*)d_in[0];
    const float* enc_w = (const float*)d_in[1];
    const float* enc_b = (const float*)d_in[2];
    const float* mem   = (const float*)d_in[3];
    const float* dec_w = (const float*)d_in[4];
    const float* dec_b = (const float*)d_in[5];

    float* out   = (float*)d_out;
    float* recon = out;
    float* att   = out + (size_t)NTOK * D_IN;
    float* memo  = att + (size_t)NTOK * MSLOTS;

    __half *E, *EW, *MEM, *MT, *W2T;
    cudaGetSymbolAddress((void**)&E, g_E);
    cudaGetSymbolAddress((void**)&EW, g_EW);
    cudaGetSymbolAddress((void**)&MEM, g_MEM);
    cudaGetSymbolAddress((void**)&MT, g_MT);
    cudaGetSymbolAddress((void**)&W2T, g_W2T);

    const int SM_G1 = 2 * 18432 + 2 * 10240 + 10240;   // 67584
    const int SM_AF = 30720 + 2 * 18432;               // 67584
    cudaFuncSetAttribute(gemm_enc,   cudaFuncAttributeMaxDynamicSharedMemorySize, SM_G1);
    cudaFuncSetAttribute(attn_fused, cudaFuncAttributeMaxDynamicSharedMemorySize, SM_AF);

    // prep (one launch)
    {
        const int nW = 32768 + 4096 + 16384 + 32768;   // 86016
        prep_weights<<<(nW + 255) / 256, 256>>>(enc_w, mem, dec_w,
                                                (__half2*)EW, (__half2*)MEM,
                                                MT, W2T);
    }

    // 1) encoded = tanh(seq @ enc_w^T + enc_b) -> fp16 (seq converted inline)
    {
        dim3 grid(D_K / 128, NTOK / 128);
        gemm_enc<<<grid, 256, SM_G1>>>(seq, EW, enc_b, E);
    }
    // 2) fused logits + softmax + memo + recon
    attn_fused<<<NTOK / 128, 256, SM_AF>>>(E, MEM, MT, W2T, dec_b,
                                           att, memo, recon);
}